// round 11
// baseline (speedup 1.0000x reference)
#include <cuda_runtime.h>
#include <math.h>

#define Bn 2
#define Cn 96
#define Hn 128
#define Wn 256
#define WFn 129
#define HWn (Hn*Wn)
#define AUXn 101
#define MIDn 24
#define DMIDn 50
#define NTOT (Bn*Cn*HWn)
#define NF (Bn*Cn*Hn*WFn)
#define CDIV(a,b) (((a)+(b)-1)/(b))

typedef unsigned long long u64;

__device__ __forceinline__ u64 ffma2(u64 a, u64 b, u64 c) {
    u64 d;
    asm("fma.rn.f32x2 %0, %1, %2, %3;" : "=l"(d) : "l"(a), "l"(b), "l"(c));
    return d;
}
__device__ __forceinline__ float2 unpack2(u64 v) {
    float2 d; asm("mov.b64 {%0, %1}, %2;" : "=f"(d.x), "=f"(d.y) : "l"(v)); return d;
}

// ------------------------- scratch (static device memory) -------------------
static __device__ float2 g_tw[128];
static __device__ float2 g_fft[(size_t)NF];
static __device__ float g_mag[NF];
static __device__ float g_fe[Bn*Hn*WFn];
static __device__ float g_fem[Bn*Hn*WFn];
static __device__ float g_gvec[Bn*3*Cn];
static __device__ float g_ca[Bn*Cn];
static __device__ float g_s0[Bn*3*HWn];
static __device__ float g_sa[Bn*HWn];
static __device__ float g_aux[(size_t)Bn*AUXn*HWn];
static __device__ float g_offb[Bn*18*HWn];
static __device__ float g_gate[Bn*HWn];
static __device__ float g_ybase[NTOT];
static __device__ float g_z[NTOT];
static __device__ float g_mu[Cn];
static __device__ float g_istd[Cn];
// pre-packed duplicated (w,w) weight tables (float4-aligned)
static __device__ float4 g_wpk68[31824];   // [104][68][9] float2
static __device__ float4 g_wpk96[41472];   // [96][96][9] float2
static __device__ float4 g_defw2[41472];   // [9][96][96] float2

// ------------------------- prep kernels -------------------------------------
__global__ void prep_tw_k() {
    int j = threadIdx.x;           // 128
    float ang = -6.2831853071795864f * (float)j / 256.f;
    float s, c; sincosf(ang, &s, &c);
    g_tw[j] = make_float2(c, s);
}
__global__ void prep_w68_k(const float* __restrict__ offw, const float* __restrict__ dg1w) {
    int i = blockIdx.x*256 + threadIdx.x;
    if (i >= 104*68*9) return;
    int ci = i / 612; int rem = i - ci*612; int o = rem / 9; int j = rem - o*9;
    float v = 0.f;
    if (ci < AUXn) {
        if (o < 18) v = offw[((size_t)o*AUXn + ci)*9 + j];
        else        v = dg1w[((size_t)(o-18)*AUXn + ci)*9 + j];
    }
    ((float2*)g_wpk68)[i] = make_float2(v, v);
}
__global__ void prep_w96_k(const float* __restrict__ basew) {
    int i = blockIdx.x*256 + threadIdx.x;
    if (i >= 96*96*9) return;
    int ci = i / 864; int rem = i - ci*864; int o = rem / 9; int j = rem - o*9;
    float v = basew[((size_t)o*96 + ci)*9 + j];
    ((float2*)g_wpk96)[i] = make_float2(v, v);
}
__global__ void prep_defw2_k(const float* __restrict__ defw) {
    int i = blockIdx.x*256 + threadIdx.x;
    if (i >= 9*96*96) return;
    int o = i % 96; int c = (i / 96) % 96; int t = i / (96*96);
    float v = defw[((size_t)o*96 + c)*9 + t];
    ((float2*)g_defw2)[i] = make_float2(v, v);
}

// ------------------------- FFT kernels (split, high-parallel) ---------------
__global__ void fft_rows_k(const float* __restrict__ in, int cstride) {
    __shared__ float re[256], im[256];
    __shared__ float2 tws[128];
    int h0 = blockIdx.x * 2;
    int c = blockIdx.y, b = blockIdx.z;
    const float* r0 = in + ((size_t)(b*cstride + c)*Hn + h0)*Wn;
    const float* r1 = r0 + Wn;
    int tid = threadIdx.x;                // 128
    tws[tid] = g_tw[tid];
    for (int i = tid; i < 256; i += 128) {
        int j = __brev((unsigned)i) >> 24;
        re[j] = r0[i];
        im[j] = r1[i];
    }
    __syncthreads();
    #pragma unroll
    for (int s = 1; s <= 8; s++) {
        int half = 1 << (s - 1);
        int i = tid;
        int off = i & (half - 1);
        int a = ((i >> (s - 1)) << s) + off;
        int bb = a + half;
        float2 tw = tws[off << (8 - s)];
        float br = re[bb], bi = im[bb];
        float ar = re[a],  ai = im[a];
        float xr = br*tw.x - bi*tw.y;
        float xi = br*tw.y + bi*tw.x;
        re[a] = ar + xr; im[a] = ai + xi;
        re[bb] = ar - xr; im[bb] = ai - xi;
        __syncthreads();
    }
    float2* out0 = g_fft + ((size_t)(b*Cn + c)*Hn + h0)*WFn;
    float2* out1 = out0 + WFn;
    int k = tid;
    float zr = re[k], zi = im[k];
    int km = (256 - k) & 255;
    float wr = re[km], wi = im[km];
    out0[k] = make_float2(0.5f*(zr + wr), 0.5f*(zi - wi));
    out1[k] = make_float2(0.5f*(zi + wi), -0.5f*(zr - wr));
    if (tid == 0) {
        out0[128] = make_float2(re[128], 0.f);
        out1[128] = make_float2(im[128], 0.f);
    }
}

// fused: y = x*ca*sa (written to g_aux) + row FFT of y
__global__ void fft_rows_y_k(const float* __restrict__ x) {
    __shared__ float re[256], im[256];
    __shared__ float2 tws[128];
    int h0 = blockIdx.x * 2;
    int c = blockIdx.y, b = blockIdx.z;
    const float* r0 = x + ((size_t)(b*Cn + c)*Hn + h0)*Wn;
    const float* r1 = r0 + Wn;
    float* y0 = g_aux + ((size_t)(b*AUXn + c)*Hn + h0)*Wn;
    float* y1 = y0 + Wn;
    const float* sa0 = g_sa + (size_t)b*HWn + h0*Wn;
    const float* sa1 = sa0 + Wn;
    float cav = g_ca[b*Cn + c];
    int tid = threadIdx.x;                // 128
    tws[tid] = g_tw[tid];
    for (int i = tid; i < 256; i += 128) {
        int j = __brev((unsigned)i) >> 24;
        float v0 = r0[i]*cav*sa0[i];
        float v1 = r1[i]*cav*sa1[i];
        y0[i] = v0; y1[i] = v1;
        re[j] = v0;
        im[j] = v1;
    }
    __syncthreads();
    #pragma unroll
    for (int s = 1; s <= 8; s++) {
        int half = 1 << (s - 1);
        int i = tid;
        int off = i & (half - 1);
        int a = ((i >> (s - 1)) << s) + off;
        int bb = a + half;
        float2 tw = tws[off << (8 - s)];
        float br = re[bb], bi = im[bb];
        float ar = re[a],  ai = im[a];
        float xr = br*tw.x - bi*tw.y;
        float xi = br*tw.y + bi*tw.x;
        re[a] = ar + xr; im[a] = ai + xi;
        re[bb] = ar - xr; im[bb] = ai - xi;
        __syncthreads();
    }
    float2* out0 = g_fft + ((size_t)(b*Cn + c)*Hn + h0)*WFn;
    float2* out1 = out0 + WFn;
    int k = tid;
    float zr = re[k], zi = im[k];
    int km = (256 - k) & 255;
    float wr = re[km], wi = im[km];
    out0[k] = make_float2(0.5f*(zr + wr), 0.5f*(zi - wi));
    out1[k] = make_float2(0.5f*(zi + wi), -0.5f*(zr - wr));
    if (tid == 0) {
        out0[128] = make_float2(re[128], 0.f);
        out1[128] = make_float2(im[128], 0.f);
    }
}

// 128-pt FFT down columns, 16 columns per block (coalesced), |.| * 1/sqrt(HW)
__global__ void fft_cols_k() {
    __shared__ float cre[16][129];
    __shared__ float cim[16][129];
    __shared__ float2 tws[128];
    int kb = blockIdx.x;                  // 0..8
    int c = blockIdx.y, b = blockIdx.z;
    int bc = b*Cn + c;
    int k0 = kb * 16;
    int ncols = (kb < 8) ? 16 : 1;
    int lg = (kb < 8) ? 4 : 0;
    int tid = threadIdx.x;                // 128
    tws[tid] = g_tw[tid];
    int kk = tid & 15, ht = tid >> 4;
    const float2* src = g_fft + (size_t)bc*Hn*WFn;
    for (int hb = 0; hb < 16; hb++) {
        int h = hb*8 + ht;
        if (kk < ncols) {
            float2 v = src[(size_t)h*WFn + k0 + kk];
            int j = __brev((unsigned)h) >> 25;
            cre[kk][j] = v.x; cim[kk][j] = v.y;
        }
    }
    __syncthreads();
    #pragma unroll
    for (int s = 1; s <= 7; s++) {
        int half = 1 << (s - 1);
        int total = ncols << 6;
        for (int e = tid; e < total; e += 128) {
            int col = e & (ncols - 1);
            int i = e >> lg;
            int off = i & (half - 1);
            int a = ((i >> (s - 1)) << s) + off;
            int bb = a + half;
            float2 tw = tws[off << (8 - s)];
            float br = cre[col][bb], bi = cim[col][bb];
            float ar = cre[col][a],  ai = cim[col][a];
            float xr = br*tw.x - bi*tw.y;
            float xi = br*tw.y + bi*tw.x;
            cre[col][a] = ar + xr; cim[col][a] = ai + xi;
            cre[col][bb] = ar - xr; cim[col][bb] = ai - xi;
        }
        __syncthreads();
    }
    const float sc = 0.0055242717280199026f;  // 1/sqrt(128*256)
    float* dst = g_mag + (size_t)bc*Hn*WFn;
    int total = ncols << 7;
    for (int e = tid; e < total; e += 128) {
        int col = e & (ncols - 1);
        int h = e >> lg;
        float r = cre[col][h], m = cim[col][h];
        dst[(size_t)h*WFn + k0 + col] = sqrtf(r*r + m*m) * sc;
    }
}

// mean over channels of g_mag -> out[b][h][k]
__global__ void chan_mean_k(float* __restrict__ out) {
    int h = blockIdx.x, b = blockIdx.y;
    for (int k = threadIdx.x; k < WFn; k += 160) {
        float s = 0.f;
        const float* p = g_mag + ((size_t)(b*Cn)*Hn + h)*WFn + k;
        #pragma unroll 4
        for (int c = 0; c < Cn; c++) s += p[(size_t)c*Hn*WFn];
        out[(size_t)(b*Hn + h)*WFn + k] = s * (1.f/Cn);
    }
}

// --------- fused freq branch: direct 49-tap separable stencil + pools -------
__global__ __launch_bounds__(512)
void freq_fused_k(const float* __restrict__ w7h, const float* __restrict__ b7h,
                  const float* __restrict__ w7w, const float* __restrict__ b7w) {
    extern __shared__ float A[];          // [128][132]
    __shared__ float S[4][132];
    __shared__ float bins[21];
    int c = blockIdx.x, b = blockIdx.y;
    int tid = threadIdx.x;
    const float* mp = g_mag + (size_t)(b*Cn + c)*Hn*WFn;
    for (int e = tid; e < 128*129; e += 512) {
        int h = e / 129, k = e - h*129;
        A[h*132 + k] = mp[e];
    }
    float wh[7], ww[7];
    #pragma unroll
    for (int d = 0; d < 7; d++) { wh[d] = w7h[c*7+d]; ww[d] = w7w[c*7+d]; }
    float bh = b7h[c], bw = b7w[c];
    __syncthreads();
    for (int t = tid; t < 4*129; t += 512) {
        int band = t / 129, k = t - band*129;
        float acc = 0.f;
        for (int hh = 0; hh < 32; hh++) {
            int h = band*32 + hh;
            float t2 = bw;
            #pragma unroll
            for (int d = 0; d < 7; d++) {
                int kk = k + d - 3;
                if (kk >= 0 && kk < 129) {
                    float t1 = bh;
                    #pragma unroll
                    for (int e = 0; e < 7; e++) {
                        int h2 = h + e - 3;
                        if (h2 >= 0 && h2 < 128) t1 += wh[e]*A[h2*132 + kk];
                    }
                    t2 += ww[d]*t1;
                }
            }
            acc += t2;
        }
        S[band][k] = acc;
    }
    __syncthreads();
    if (tid < 16) {
        int i = tid >> 2, j = tid & 3;
        int ws = (j*WFn)/4, we = ((j+1)*WFn + 3)/4;
        float s = 0;
        for (int k = ws; k < we; k++) s += S[i][k];
        bins[tid] = s / (32.f * (float)(we - ws));
    } else if (tid < 20) {
        int t2 = tid - 16; int i = t2 >> 1, j = t2 & 1;
        int ws = (j*WFn)/2, we = ((j+1)*WFn + 1)/2;
        float s = 0;
        for (int k = ws; k < we; k++) s += S[2*i][k] + S[2*i+1][k];
        bins[tid] = s / (64.f * (float)(we - ws));
    } else if (tid == 20) {
        float s = 0;
        for (int k = 0; k < WFn; k++) s += S[0][k]+S[1][k]+S[2][k]+S[3][k];
        bins[20] = s / (128.f*129.f);
    }
    __syncthreads();
    if (tid == 0) {
        float g2 = bins[16]+bins[17]+bins[18]+bins[19];
        float g3 = 0;
        for (int m = 0; m < 16; m++) g3 += bins[m];
        g_gvec[b*288 + c]        = bins[20];
        g_gvec[b*288 + Cn + c]   = g2 * 0.25f;
        g_gvec[b*288 + 2*Cn + c] = g3 * 0.0625f;
    }
}

// ------------------------- channel-attention MLP ----------------------------
__global__ void ca_mlp_k(const float* __restrict__ w1, const float* __restrict__ b1,
                         const float* __restrict__ w2, const float* __restrict__ b2) {
    __shared__ float gs[288], hs[MIDn];
    int b = blockIdx.x, tid = threadIdx.x;   // 96 threads
    for (int i = tid; i < 288; i += 96) gs[i] = g_gvec[b*288 + i];
    __syncthreads();
    if (tid < MIDn) {
        float a = b1[tid];
        for (int k = 0; k < 288; k++) a += w1[tid*288 + k]*gs[k];
        hs[tid] = fmaxf(a, 0.f);
    }
    __syncthreads();
    float a = b2[tid];
    #pragma unroll
    for (int m = 0; m < MIDn; m++) a += w2[tid*MIDn + m]*hs[m];
    g_ca[b*Cn + tid] = 1.f/(1.f + expf(-a));
}

// ------------------------- spatial branch -----------------------------------
__global__ void spatial_in_k(const float* __restrict__ x) {
    int h = blockIdx.x, b = blockIdx.y;
    int w = threadIdx.x;                  // 256
    int hw = h*Wn + w;
    const float* xp = x + (size_t)b*Cn*HWn + hw;
    float s = 0.f, s2 = 0.f;
    #pragma unroll 4
    for (int c = 0; c < Cn; c++) { float v = xp[(size_t)c*HWn]; s += v; s2 += v*v; }
    float mean = s * (1.f/Cn);
    float l2 = sqrtf(s2 * (1.f/Cn) + 1e-6f);
    float src = ((float)w + 0.5f)*(129.f/256.f) - 0.5f;
    float f0 = floorf(src); int i0 = (int)f0; float fr = src - f0;
    int ia = min(max(i0, 0), WFn-1), ib = min(max(i0+1, 0), WFn-1);
    const float* fp = g_fe + (size_t)(b*Hn + h)*WFn;
    float fv = fp[ia]*(1.f - fr) + fp[ib]*fr;
    g_s0[((size_t)(b*3+0))*HWn + hw] = mean;
    g_s0[((size_t)(b*3+1))*HWn + hw] = l2;
    g_s0[((size_t)(b*3+2))*HWn + hw] = fv;
}

// fused dwsp_h + dwsp_w + sr: one block per (h, b); 256 threads (w)
__global__ __launch_bounds__(256)
void sp_fused_k(const float* __restrict__ w15h, const float* __restrict__ b15h,
                const float* __restrict__ w15w, const float* __restrict__ b15w,
                const float* __restrict__ sr1w, const float* __restrict__ sr1b,
                const float* __restrict__ sr2w, const float* __restrict__ sr2b) {
    __shared__ float s1buf[3][3][272];
    __shared__ float sbuf[3][3][258];
    __shared__ float wsm[3][15], wsw[3][15];
    int h = blockIdx.x, b = blockIdx.y;
    int w = threadIdx.x;                 // 256
    if (w < 45) { wsm[w/15][w%15] = w15h[w]; wsw[w/15][w%15] = w15w[w]; }
    if (w < 7) {
        #pragma unroll
        for (int ch = 0; ch < 3; ch++)
            #pragma unroll
            for (int j = 0; j < 3; j++) { s1buf[ch][j][w] = 0.f; s1buf[ch][j][263+w] = 0.f; }
    }
    if (w < 9) {
        #pragma unroll
        for (int ch = 0; ch < 3; ch++)
            #pragma unroll
            for (int j = 0; j < 3; j++) s1buf[ch][j][263+w] = 0.f;
    }
    if (w < 3) {
        #pragma unroll
        for (int ch = 0; ch < 3; ch++) { sbuf[ch][w][0] = 0.f; sbuf[ch][w][257] = 0.f; }
    }
    __syncthreads();
    #pragma unroll
    for (int ch = 0; ch < 3; ch++) {
        const float* s0p = g_s0 + ((size_t)(b*3 + ch))*HWn + w;
        #pragma unroll
        for (int j = 0; j < 3; j++) {
            int hr = h + j - 1;
            float a = b15h[ch];
            #pragma unroll
            for (int d = 0; d < 15; d++) {
                int hh = hr + d - 7;
                if (hh >= 0 && hh < Hn) a += wsm[ch][d]*s0p[hh*Wn];
            }
            s1buf[ch][j][7 + w] = a;
        }
    }
    __syncthreads();
    #pragma unroll
    for (int ch = 0; ch < 3; ch++) {
        #pragma unroll
        for (int j = 0; j < 3; j++) {
            float a = b15w[ch];
            #pragma unroll
            for (int d = 0; d < 15; d++) a += wsw[ch][d]*s1buf[ch][j][w + d];
            sbuf[ch][j][1 + w] = a;
        }
    }
    __syncthreads();
    float acc = sr2b[0];
    #pragma unroll
    for (int ch = 0; ch < 3; ch++) {
        float v = sr1b[ch];
        #pragma unroll
        for (int ky = 0; ky < 3; ky++) {
            int hh = h + ky - 1; if (hh < 0 || hh >= Hn) continue;
            #pragma unroll
            for (int kx = 0; kx < 3; kx++) {
                v += sr1w[ch*9 + ky*3 + kx]*sbuf[ch][ky][w + kx];
            }
        }
        acc += sr2w[ch]*fmaxf(v, 0.f);
    }
    g_sa[(size_t)b*HWn + h*Wn + w] = 1.f/(1.f + expf(-acc));
}

__global__ void auxmisc_k() {
    int h = blockIdx.x, b = blockIdx.y;
    int w = threadIdx.x;                 // 256
    int hw = h*Wn + w;
    float theta = -3.14159265358979324f + (float)w * (6.2831853071795864f/255.f);
    float phi   = -1.57079632679489662f + (float)h * (3.14159265358979324f/127.f);
    size_t base = (size_t)b*AUXn*HWn + hw;
    g_aux[base + (size_t)96*HWn] = sinf(theta);
    g_aux[base + (size_t)97*HWn] = cosf(theta);
    g_aux[base + (size_t)98*HWn] = sinf(phi);
    g_aux[base + (size_t)99*HWn] = cosf(phi);
    float src = ((float)w + 0.5f)*(129.f/256.f) - 0.5f;
    float f0 = floorf(src); int i0 = (int)f0; float fr = src - f0;
    int ia = min(max(i0, 0), WFn-1), ib = min(max(i0+1, 0), WFn-1);
    const float* fp = g_fem + (size_t)(b*Hn + h)*WFn;
    g_aux[base + (size_t)100*HWn] = fp[ia]*(1.f - fr) + fp[ib]*fr;
}

// ------------- merged offset(18)+dg1(50) conv, pre-packed weights -----------
__global__ __launch_bounds__(256)
void convoffdg_k(const float* __restrict__ offbias,
                 const float* __restrict__ dg1b,
                 const float* __restrict__ dg2w, const float* __restrict__ dg2b) {
    constexpr int COUT = 68;
    constexpr int NO = 3;
    constexpr int CB = 8;
    __shared__ float2 tile2[CB][3][66];
    __shared__ float sgate[32][64];
    extern __shared__ float2 wdyn[];          // [CB][COUT*9]
    int bx = blockIdx.x;
    int seg = bx & 3; int h = (bx >> 2) & (Hn - 1); int b = bx >> 9;
    int w0 = seg * 64;
    int tid = threadIdx.x;
    int pg = tid & 7, og = tid >> 3;
    u64 pacc[NO][4];
    #pragma unroll
    for (int k = 0; k < NO; k++)
        #pragma unroll
        for (int q = 0; q < 4; q++) pacc[k][q] = 0ull;
    const float* inb = g_aux + (size_t)b*AUXn*HWn;
    int pv8idx = (pg == 7) ? 64 : (pg + 1);
    for (int c0 = 0; c0 < AUXn; c0 += CB) {
        for (int m = tid; m < CB*3*65; m += 256) {
            int ci = m / 195; int rem = m - ci*195; int r = rem / 65; int p = rem - r*65;
            int l = (p < 64) ? (((p & 7) << 3) | (p >> 3)) : 64;
            int hh = h + r - 1, ww = w0 + l - 1;
            float v0 = 0.f, v1 = 0.f;
            if (c0 + ci < AUXn && hh >= 0 && hh < Hn) {
                const float* rowp = inb + (size_t)(c0 + ci)*HWn + (size_t)hh*Wn;
                if (ww >= 0 && ww < Wn) v0 = rowp[ww];
                if (ww + 1 >= 0 && ww + 1 < Wn) v1 = rowp[ww + 1];
            }
            tile2[ci][r][p] = make_float2(v0, v1);
        }
        {   // coalesced float4 weight copy (pre-packed, incl. zero pad rows)
            const float4* wsrc = g_wpk68 + (size_t)c0*306;
            float4* wdst = (float4*)wdyn;
            for (int m = tid; m < CB*306; m += 256) wdst[m] = wsrc[m];
        }
        __syncthreads();
        #pragma unroll 2
        for (int ci = 0; ci < CB; ci++) {
            #pragma unroll
            for (int r = 0; r < 3; r++) {
                const float2* trow = tile2[ci][r];
                u64 pv[9];
                #pragma unroll
                for (int j = 0; j < 8; j++) pv[j] = *(const u64*)&trow[j*8 + pg];
                pv[8] = *(const u64*)&trow[pv8idx];
                #pragma unroll
                for (int k = 0; k < NO; k++) {
                    int o = og + 32*k;
                    if (o >= COUT) break;
                    const u64* wp = (const u64*)&wdyn[ci*(COUT*9) + o*9 + r*3];
                    u64 wb0 = wp[0], wb1 = wp[1], wb2 = wp[2];
                    #pragma unroll
                    for (int q = 0; q < 4; q++) {
                        pacc[k][q] = ffma2(wb0, pv[2*q],   pacc[k][q]);
                        pacc[k][q] = ffma2(wb1, pv[2*q+1], pacc[k][q]);
                        pacc[k][q] = ffma2(wb2, pv[2*q+2], pacc[k][q]);
                    }
                }
            }
        }
        __syncthreads();
    }
    float part[8];
    #pragma unroll
    for (int p = 0; p < 8; p++) part[p] = 0.f;
    #pragma unroll
    for (int k = 0; k < NO; k++) {
        int o = og + 32*k;
        if (o >= COUT) break;
        if (o < 18) {
            float bb = offbias[o];
            float* op = g_offb + ((size_t)(b*18 + o))*HWn + h*Wn + w0 + pg*8;
            #pragma unroll
            for (int q = 0; q < 4; q++) {
                float2 f = unpack2(pacc[k][q]);
                op[2*q] = f.x + bb; op[2*q+1] = f.y + bb;
            }
        } else {
            float bb = dg1b[o-18];
            float wv = dg2w[o-18];
            #pragma unroll
            for (int q = 0; q < 4; q++) {
                float2 f = unpack2(pacc[k][q]);
                part[2*q]   += wv * fmaxf(f.x + bb, 0.f);
                part[2*q+1] += wv * fmaxf(f.y + bb, 0.f);
            }
        }
    }
    #pragma unroll
    for (int p = 0; p < 8; p++) sgate[og][pg*8 + p] = part[p];
    __syncthreads();
    if (tid < 64) {
        float s = dg2b[0];
        #pragma unroll 8
        for (int o2 = 0; o2 < 32; o2++) s += sgate[o2][tid];
        g_gate[(size_t)b*HWn + h*Wn + w0 + tid] = 1.f/(1.f + expf(-s));
    }
}

// ------------- base 3x3 conv (96->96), pre-packed weights -------------------
__global__ __launch_bounds__(256)
void conv_base_k(const float* __restrict__ baseb) {
    constexpr int COUT = 96;
    constexpr int NO = 3;
    constexpr int CB = 8;
    __shared__ float2 tile2[CB][3][66];
    extern __shared__ float2 wdyn[];          // [CB][COUT*9]
    int bx = blockIdx.x;
    int seg = bx & 3; int h = (bx >> 2) & (Hn - 1); int b = bx >> 9;
    int w0 = seg * 64;
    int tid = threadIdx.x;
    int pg = tid & 7, og = tid >> 3;
    u64 pacc[NO][4];
    #pragma unroll
    for (int k = 0; k < NO; k++)
        #pragma unroll
        for (int q = 0; q < 4; q++) pacc[k][q] = 0ull;
    const float* inb = g_aux + (size_t)b*AUXn*HWn;
    int pv8idx = (pg == 7) ? 64 : (pg + 1);
    for (int c0 = 0; c0 < 96; c0 += CB) {
        for (int m = tid; m < CB*3*65; m += 256) {
            int ci = m / 195; int rem = m - ci*195; int r = rem / 65; int p = rem - r*65;
            int l = (p < 64) ? (((p & 7) << 3) | (p >> 3)) : 64;
            int hh = h + r - 1, ww = w0 + l - 1;
            float v0 = 0.f, v1 = 0.f;
            if (hh >= 0 && hh < Hn) {
                const float* rowp = inb + (size_t)(c0 + ci)*HWn + (size_t)hh*Wn;
                if (ww >= 0 && ww < Wn) v0 = rowp[ww];
                if (ww + 1 >= 0 && ww + 1 < Wn) v1 = rowp[ww + 1];
            }
            tile2[ci][r][p] = make_float2(v0, v1);
        }
        {
            const float4* wsrc = g_wpk96 + (size_t)c0*432;
            float4* wdst = (float4*)wdyn;
            for (int m = tid; m < CB*432; m += 256) wdst[m] = wsrc[m];
        }
        __syncthreads();
        #pragma unroll 2
        for (int ci = 0; ci < CB; ci++) {
            #pragma unroll
            for (int r = 0; r < 3; r++) {
                const float2* trow = tile2[ci][r];
                u64 pv[9];
                #pragma unroll
                for (int j = 0; j < 8; j++) pv[j] = *(const u64*)&trow[j*8 + pg];
                pv[8] = *(const u64*)&trow[pv8idx];
                #pragma unroll
                for (int k = 0; k < NO; k++) {
                    int o = og + 32*k;
                    const u64* wp = (const u64*)&wdyn[ci*(COUT*9) + o*9 + r*3];
                    u64 wb0 = wp[0], wb1 = wp[1], wb2 = wp[2];
                    #pragma unroll
                    for (int q = 0; q < 4; q++) {
                        pacc[k][q] = ffma2(wb0, pv[2*q],   pacc[k][q]);
                        pacc[k][q] = ffma2(wb1, pv[2*q+1], pacc[k][q]);
                        pacc[k][q] = ffma2(wb2, pv[2*q+2], pacc[k][q]);
                    }
                }
            }
        }
        __syncthreads();
    }
    #pragma unroll
    for (int k = 0; k < NO; k++) {
        int o = og + 32*k;
        float bb = baseb[o];
        float* op = g_ybase + ((size_t)(b*COUT + o))*HWn + h*Wn + w0 + pg*8;
        #pragma unroll
        for (int q = 0; q < 4; q++) {
            float2 f = unpack2(pacc[k][q]);
            op[2*q] = f.x + bb; op[2*q+1] = f.y + bb;
        }
    }
}

// ------------------------- deformable sampling + GEMM + combine -------------
__global__ __launch_bounds__(256)
void deform_combine_k(const float* __restrict__ defb) {
    extern __shared__ float dsm[];
    float2* samp2 = (float2*)dsm;                    // 2304 float2
    float2* wsh2  = (float2*)(dsm + 4608);           // 6912 float2
    float*  s_w   = dsm + 18432;                     // 2304
    int*    s_idx = (int*)(dsm + 20736);             // 2304
    int bx = blockIdx.x;
    int seg = bx & 3; int h = (bx >> 2) & (Hn - 1); int b = bx >> 9;
    int w0 = seg * 64;
    int tid = threadIdx.x;
    int pg = tid & 7, og = tid >> 3;

    for (int e = tid; e < 576; e += 256) {
        int t9 = e >> 6, p = e & 63;
        int wpx = w0 + p;
        size_t obase = ((size_t)b*18)*HWn + (size_t)h*Wn + wpx;
        float ox = g_offb[obase + (size_t)(2*t9)*HWn];
        float oy = g_offb[obase + (size_t)(2*t9+1)*HWn];
        float px = (float)wpx + ox;
        float py = (float)h + oy;
        float x0 = floorf(px), y0 = floorf(py);
        float fx = px - x0, fy = py - y0;
        #pragma unroll
        for (int j = 0; j < 4; j++) {
            float xj = x0 + (float)(j & 1);
            float yj = y0 + (float)(j >> 1);
            float valid = (xj >= 0.f && xj <= 255.f && yj >= 0.f && yj <= 127.f) ? 1.f : 0.f;
            float xc = fminf(fmaxf(xj, 0.f), 255.f);
            float yc = fminf(fmaxf(yj, 0.f), 127.f);
            s_idx[(t9*64 + p)*4 + j] = (int)yc * Wn + (int)xc;
            float wx = (j & 1) ? fx : (1.f - fx);
            float wy = (j >> 1) ? fy : (1.f - fy);
            s_w[(t9*64 + p)*4 + j] = wx * wy * valid;
        }
    }

    u64 pacc[3][4];
    #pragma unroll
    for (int k = 0; k < 3; k++)
        #pragma unroll
        for (int q = 0; q < 4; q++) pacc[k][q] = 0ull;

    for (int c0 = 0; c0 < 96; c0 += 8) {
        __syncthreads();
        for (int e = tid; e < 2304; e += 256) {
            int t9 = e >> 8; int rem = e & 255; int c = rem >> 5; int P = rem & 31;
            int p0 = 2*P;
            const float* yp = g_aux + ((size_t)(b*AUXn + c0 + c))*HWn;
            const int* i0 = &s_idx[(t9*64 + p0)*4];
            const float* q0 = &s_w[(t9*64 + p0)*4];
            float v0 = q0[0]*yp[i0[0]] + q0[1]*yp[i0[1]] + q0[2]*yp[i0[2]] + q0[3]*yp[i0[3]];
            const int* i1 = i0 + 4; const float* q1 = q0 + 4;
            float v1 = q1[0]*yp[i1[0]] + q1[1]*yp[i1[1]] + q1[2]*yp[i1[2]] + q1[3]*yp[i1[3]];
            samp2[(t9*8 + c)*32 + (((P & 3) << 3) | (P >> 2))] = make_float2(v0, v1);
        }
        {   // coalesced float4 weight copy from pre-packed dup table
            float4* wdst = (float4*)wsh2;
            for (int e4 = tid; e4 < 3456; e4 += 256) {
                int t9 = e4 / 384; int off4 = e4 - t9*384;
                wdst[e4] = g_defw2[(size_t)(t9*96 + c0)*48 + off4];
            }
        }
        __syncthreads();
        #pragma unroll 3
        for (int t9 = 0; t9 < 9; t9++) {
            #pragma unroll
            for (int c = 0; c < 8; c++) {
                const float2* sp = &samp2[(t9*8 + c)*32];
                u64 s0 = *(const u64*)&sp[0*8 + pg];
                u64 s1 = *(const u64*)&sp[1*8 + pg];
                u64 s2 = *(const u64*)&sp[2*8 + pg];
                u64 s3 = *(const u64*)&sp[3*8 + pg];
                const float2* wb = &wsh2[(t9*8 + c)*96];
                #pragma unroll
                for (int k = 0; k < 3; k++) {
                    u64 wp2 = *(const u64*)&wb[og + 32*k];
                    pacc[k][0] = ffma2(wp2, s0, pacc[k][0]);
                    pacc[k][1] = ffma2(wp2, s1, pacc[k][1]);
                    pacc[k][2] = ffma2(wp2, s2, pacc[k][2]);
                    pacc[k][3] = ffma2(wp2, s3, pacc[k][3]);
                }
            }
        }
    }
    #pragma unroll
    for (int k = 0; k < 3; k++) {
        int o = og + 32*k;
        float bb = defb[o];
        size_t rowoff = (size_t)h*Wn + w0 + pg*8;
        float* zp = g_z + ((size_t)(b*Cn + o))*HWn + rowoff;
        const float* yb = g_ybase + ((size_t)(b*Cn + o))*HWn + rowoff;
        const float* gp = g_gate + (size_t)b*HWn + rowoff;
        #pragma unroll
        for (int q = 0; q < 4; q++) {
            float2 f = unpack2(pacc[k][q]);
            float g0 = gp[2*q], g1 = gp[2*q+1];
            zp[2*q]   = (1.f - g0)*yb[2*q]   + g0*(f.x + bb);
            zp[2*q+1] = (1.f - g1)*yb[2*q+1] + g1*(f.y + bb);
        }
    }
}

// ------------------------- batchnorm (float4) -------------------------------
__global__ void bn_stats_k() {
    __shared__ float ss[256], ss2[256];
    int c = blockIdx.x, tid = threadIdx.x;
    float s = 0.f, s2 = 0.f;
    for (int b = 0; b < Bn; b++) {
        const float4* zp = (const float4*)(g_z + ((size_t)(b*Cn + c))*HWn);
        for (int i = tid; i < HWn/4; i += 256) {
            float4 v = zp[i];
            s += v.x + v.y + v.z + v.w;
            s2 += v.x*v.x + v.y*v.y + v.z*v.z + v.w*v.w;
        }
    }
    ss[tid] = s; ss2[tid] = s2;
    __syncthreads();
    for (int st = 128; st > 0; st >>= 1) {
        if (tid < st) { ss[tid] += ss[tid+st]; ss2[tid] += ss2[tid+st]; }
        __syncthreads();
    }
    if (tid == 0) {
        float inv = 1.f/(float)(Bn*HWn);
        float mu = ss[0]*inv;
        float var = ss2[0]*inv - mu*mu;
        g_mu[c] = mu;
        g_istd[c] = rsqrtf(var + 1e-5f);
    }
}

__global__ void bn_apply_k(const float* __restrict__ x,
                           const float* __restrict__ gam, const float* __restrict__ bet,
                           float* __restrict__ out) {
    int e = blockIdx.x*256 + threadIdx.x;
    int c = blockIdx.y, b = blockIdx.z;
    size_t i4 = ((size_t)(b*Cn + c))*(HWn/4) + e;
    float sc2 = g_istd[c]*gam[c];
    float sh = bet[c] - g_mu[c]*sc2;
    float4 z = ((const float4*)g_z)[i4];
    float4 xv = ((const float4*)x)[i4];
    float4 o;
    o.x = fmaxf(z.x*sc2 + sh + xv.x, 0.f);
    o.y = fmaxf(z.y*sc2 + sh + xv.y, 0.f);
    o.z = fmaxf(z.z*sc2 + sh + xv.z, 0.f);
    o.w = fmaxf(z.w*sc2 + sh + xv.w, 0.f);
    ((float4*)out)[i4] = o;
}

// ------------------------- launch -------------------------------------------
extern "C" void kernel_launch(void* const* d_in, const int* in_sizes, int n_in,
                              void* d_out, int out_size) {
    const float* x     = (const float*)d_in[0];
    const float* fdh_w = (const float*)d_in[1];
    const float* fdh_b = (const float*)d_in[2];
    const float* fdw_w = (const float*)d_in[3];
    const float* fdw_b = (const float*)d_in[4];
    const float* cp1_w = (const float*)d_in[5];
    const float* cp1_b = (const float*)d_in[6];
    const float* cp2_w = (const float*)d_in[7];
    const float* cp2_b = (const float*)d_in[8];
    const float* sdh_w = (const float*)d_in[9];
    const float* sdh_b = (const float*)d_in[10];
    const float* sdw_w = (const float*)d_in[11];
    const float* sdw_b = (const float*)d_in[12];
    const float* sr1_w = (const float*)d_in[13];
    const float* sr1_b = (const float*)d_in[14];
    const float* sr2_w = (const float*)d_in[15];
    const float* sr2_b = (const float*)d_in[16];
    const float* off_w = (const float*)d_in[17];
    const float* off_b = (const float*)d_in[18];
    const float* dg1_w = (const float*)d_in[19];
    const float* dg1_b = (const float*)d_in[20];
    const float* dg2_w = (const float*)d_in[21];
    const float* dg2_b = (const float*)d_in[22];
    const float* base_w = (const float*)d_in[23];
    const float* base_b = (const float*)d_in[24];
    const float* def_w = (const float*)d_in[25];
    const float* def_b = (const float*)d_in[26];
    const float* bn_g  = (const float*)d_in[27];
    const float* bn_b  = (const float*)d_in[28];
    float* out = (float*)d_out;

    float *p_fe, *p_fem;
    cudaGetSymbolAddress((void**)&p_fe, g_fe);
    cudaGetSymbolAddress((void**)&p_fem, g_fem);

    const int FREQ_SMEM = 128*132*4;         // 67584 B
    const int DEF_SMEM  = 23040 * 4;         // 92160 B
    const int C96_SMEM  = 8*96*9*8;          // 55296 B
    const int C68_SMEM  = 8*68*9*8;          // 39168 B
    cudaFuncSetAttribute(freq_fused_k, cudaFuncAttributeMaxDynamicSharedMemorySize, FREQ_SMEM);
    cudaFuncSetAttribute(deform_combine_k, cudaFuncAttributeMaxDynamicSharedMemorySize, DEF_SMEM);
    cudaFuncSetAttribute(conv_base_k, cudaFuncAttributeMaxDynamicSharedMemorySize, C96_SMEM);
    cudaFuncSetAttribute(convoffdg_k, cudaFuncAttributeMaxDynamicSharedMemorySize, C68_SMEM);

    prep_tw_k<<<1, 128>>>();
    prep_w68_k<<<CDIV(104*68*9,256), 256>>>(off_w, dg1_w);
    prep_w96_k<<<CDIV(96*96*9,256), 256>>>(base_w);
    prep_defw2_k<<<CDIV(9*96*96,256), 256>>>(def_w);
    // ---- FFT(x) -> mag, fe ----
    fft_rows_k<<<dim3(Hn/2, Cn, Bn), 128>>>(x, Cn);
    fft_cols_k<<<dim3(9, Cn, Bn), 128>>>();
    chan_mean_k<<<dim3(Hn, Bn), 160>>>(p_fe);
    // ---- freq branch ----
    freq_fused_k<<<dim3(Cn, Bn), 512, FREQ_SMEM>>>(fdh_w, fdh_b, fdw_w, fdw_b);
    ca_mlp_k<<<Bn, 96>>>(cp1_w, cp1_b, cp2_w, cp2_b);
    // ---- spatial branch (fused) ----
    spatial_in_k<<<dim3(Hn, Bn), 256>>>(x);
    sp_fused_k<<<dim3(Hn, Bn), 256>>>(sdh_w, sdh_b, sdw_w, sdw_b,
                                      sr1_w, sr1_b, sr2_w, sr2_b);
    // ---- y = x*ca*sa (into aux) + FFT(y) rows, fused ----
    fft_rows_y_k<<<dim3(Hn/2, Cn, Bn), 128>>>(x);
    fft_cols_k<<<dim3(9, Cn, Bn), 128>>>();
    chan_mean_k<<<dim3(Hn, Bn), 160>>>(p_fem);
    auxmisc_k<<<dim3(Hn, Bn), 256>>>();
    // ---- convs (separate: offset+dg1/gate; base) ----
    convoffdg_k<<<1024, 256, C68_SMEM>>>(off_b, dg1_b, dg2_w, dg2_b);
    conv_base_k<<<1024, 256, C96_SMEM>>>(base_b);
    // ---- deformable ----
    deform_combine_k<<<1024, 256, DEF_SMEM>>>(def_b);
    // ---- BN + residual relu ----
    bn_stats_k<<<Cn, 256>>>();
    bn_apply_k<<<dim3(HWn/1024, Cn, Bn), 256>>>(x, bn_g, bn_b, out);
}

// round 12
// speedup vs baseline: 1.0242x; 1.0242x over previous
#include <cuda_runtime.h>
#include <math.h>

#define Bn 2
#define Cn 96
#define Hn 128
#define Wn 256
#define WFn 129
#define HWn (Hn*Wn)
#define AUXn 101
#define MIDn 24
#define DMIDn 50
#define NTOT (Bn*Cn*HWn)
#define NF (Bn*Cn*Hn*WFn)
#define CDIV(a,b) (((a)+(b)-1)/(b))

typedef unsigned long long u64;

__device__ __forceinline__ u64 ffma2(u64 a, u64 b, u64 c) {
    u64 d;
    asm("fma.rn.f32x2 %0, %1, %2, %3;" : "=l"(d) : "l"(a), "l"(b), "l"(c));
    return d;
}
__device__ __forceinline__ float2 unpack2(u64 v) {
    float2 d; asm("mov.b64 {%0, %1}, %2;" : "=f"(d.x), "=f"(d.y) : "l"(v)); return d;
}

// ------------------------- scratch (static device memory) -------------------
static __device__ float2 g_tw[128];
static __device__ float2 g_fft[(size_t)NF];
static __device__ float g_mag[NF];
static __device__ float g_fe[Bn*Hn*WFn];
static __device__ float g_fem[Bn*Hn*WFn];
static __device__ float g_gvec[Bn*3*Cn];
static __device__ float g_ca[Bn*Cn];
static __device__ float g_s0[Bn*3*HWn];
static __device__ float g_sa[Bn*HWn];
static __device__ float g_aux[(size_t)Bn*AUXn*HWn];
static __device__ float g_offb[Bn*18*HWn];
static __device__ float g_gate[Bn*HWn];
static __device__ float g_ybase[NTOT];
static __device__ float g_z[NTOT];
static __device__ float g_mu[Cn];
static __device__ float g_istd[Cn];
// pre-packed duplicated (w,w) weight tables (float4-aligned)
static __device__ float4 g_wpk68[31824];   // [104][68][9] float2
static __device__ float4 g_wpk96[41472];   // [96][96][9] float2
static __device__ float4 g_defw2[41472];   // [9][96][96] float2

// ------------------------- stream/event infra (static init) -----------------
struct SyncInfra {
    cudaStream_t s1;
    cudaEvent_t ev1, evA, ev2, evB;
    bool ok;
    SyncInfra() {
        ok = true;
        if (cudaStreamCreateWithFlags(&s1, cudaStreamNonBlocking) != cudaSuccess) { ok = false; s1 = 0; return; }
        if (cudaEventCreateWithFlags(&ev1, cudaEventDisableTiming) != cudaSuccess) { ok = false; return; }
        if (cudaEventCreateWithFlags(&evA, cudaEventDisableTiming) != cudaSuccess) { ok = false; return; }
        if (cudaEventCreateWithFlags(&ev2, cudaEventDisableTiming) != cudaSuccess) { ok = false; return; }
        if (cudaEventCreateWithFlags(&evB, cudaEventDisableTiming) != cudaSuccess) { ok = false; return; }
    }
};
static SyncInfra g_sync;

// ------------------------- merged prep kernel --------------------------------
__global__ void prep_all_k(const float* __restrict__ offw, const float* __restrict__ dg1w,
                           const float* __restrict__ basew, const float* __restrict__ defw) {
    int i = blockIdx.x*256 + threadIdx.x;
    if (i < 128) {
        float ang = -6.2831853071795864f * (float)i / 256.f;
        float s, c; sincosf(ang, &s, &c);
        g_tw[i] = make_float2(c, s);
    }
    if (i < 104*68*9) {
        int ci = i / 612; int rem = i - ci*612; int o = rem / 9; int j = rem - o*9;
        float v = 0.f;
        if (ci < AUXn) {
            if (o < 18) v = offw[((size_t)o*AUXn + ci)*9 + j];
            else        v = dg1w[((size_t)(o-18)*AUXn + ci)*9 + j];
        }
        ((float2*)g_wpk68)[i] = make_float2(v, v);
    }
    if (i < 96*96*9) {
        int ci = i / 864; int rem = i - ci*864; int o = rem / 9; int j = rem - o*9;
        float v = basew[((size_t)o*96 + ci)*9 + j];
        ((float2*)g_wpk96)[i] = make_float2(v, v);
        int o2 = i % 96; int c2 = (i / 96) % 96; int t2 = i / (96*96);
        float v2 = defw[((size_t)o2*96 + c2)*9 + t2];
        ((float2*)g_defw2)[i] = make_float2(v2, v2);
    }
}

// ------------------------- FFT kernels (split, high-parallel) ---------------
__global__ void fft_rows_k(const float* __restrict__ in, int cstride) {
    __shared__ float re[256], im[256];
    __shared__ float2 tws[128];
    int h0 = blockIdx.x * 2;
    int c = blockIdx.y, b = blockIdx.z;
    const float* r0 = in + ((size_t)(b*cstride + c)*Hn + h0)*Wn;
    const float* r1 = r0 + Wn;
    int tid = threadIdx.x;                // 128
    tws[tid] = g_tw[tid];
    for (int i = tid; i < 256; i += 128) {
        int j = __brev((unsigned)i) >> 24;
        re[j] = r0[i];
        im[j] = r1[i];
    }
    __syncthreads();
    #pragma unroll
    for (int s = 1; s <= 8; s++) {
        int half = 1 << (s - 1);
        int i = tid;
        int off = i & (half - 1);
        int a = ((i >> (s - 1)) << s) + off;
        int bb = a + half;
        float2 tw = tws[off << (8 - s)];
        float br = re[bb], bi = im[bb];
        float ar = re[a],  ai = im[a];
        float xr = br*tw.x - bi*tw.y;
        float xi = br*tw.y + bi*tw.x;
        re[a] = ar + xr; im[a] = ai + xi;
        re[bb] = ar - xr; im[bb] = ai - xi;
        __syncthreads();
    }
    float2* out0 = g_fft + ((size_t)(b*Cn + c)*Hn + h0)*WFn;
    float2* out1 = out0 + WFn;
    int k = tid;
    float zr = re[k], zi = im[k];
    int km = (256 - k) & 255;
    float wr = re[km], wi = im[km];
    out0[k] = make_float2(0.5f*(zr + wr), 0.5f*(zi - wi));
    out1[k] = make_float2(0.5f*(zi + wi), -0.5f*(zr - wr));
    if (tid == 0) {
        out0[128] = make_float2(re[128], 0.f);
        out1[128] = make_float2(im[128], 0.f);
    }
}

// fused: y = x*ca*sa (written to g_aux) + row FFT of y
__global__ void fft_rows_y_k(const float* __restrict__ x) {
    __shared__ float re[256], im[256];
    __shared__ float2 tws[128];
    int h0 = blockIdx.x * 2;
    int c = blockIdx.y, b = blockIdx.z;
    const float* r0 = x + ((size_t)(b*Cn + c)*Hn + h0)*Wn;
    const float* r1 = r0 + Wn;
    float* y0 = g_aux + ((size_t)(b*AUXn + c)*Hn + h0)*Wn;
    float* y1 = y0 + Wn;
    const float* sa0 = g_sa + (size_t)b*HWn + h0*Wn;
    const float* sa1 = sa0 + Wn;
    float cav = g_ca[b*Cn + c];
    int tid = threadIdx.x;                // 128
    tws[tid] = g_tw[tid];
    for (int i = tid; i < 256; i += 128) {
        int j = __brev((unsigned)i) >> 24;
        float v0 = r0[i]*cav*sa0[i];
        float v1 = r1[i]*cav*sa1[i];
        y0[i] = v0; y1[i] = v1;
        re[j] = v0;
        im[j] = v1;
    }
    __syncthreads();
    #pragma unroll
    for (int s = 1; s <= 8; s++) {
        int half = 1 << (s - 1);
        int i = tid;
        int off = i & (half - 1);
        int a = ((i >> (s - 1)) << s) + off;
        int bb = a + half;
        float2 tw = tws[off << (8 - s)];
        float br = re[bb], bi = im[bb];
        float ar = re[a],  ai = im[a];
        float xr = br*tw.x - bi*tw.y;
        float xi = br*tw.y + bi*tw.x;
        re[a] = ar + xr; im[a] = ai + xi;
        re[bb] = ar - xr; im[bb] = ai - xi;
        __syncthreads();
    }
    float2* out0 = g_fft + ((size_t)(b*Cn + c)*Hn + h0)*WFn;
    float2* out1 = out0 + WFn;
    int k = tid;
    float zr = re[k], zi = im[k];
    int km = (256 - k) & 255;
    float wr = re[km], wi = im[km];
    out0[k] = make_float2(0.5f*(zr + wr), 0.5f*(zi - wi));
    out1[k] = make_float2(0.5f*(zi + wi), -0.5f*(zr - wr));
    if (tid == 0) {
        out0[128] = make_float2(re[128], 0.f);
        out1[128] = make_float2(im[128], 0.f);
    }
}

// 128-pt FFT down columns, 16 columns per block (coalesced), |.| * 1/sqrt(HW)
__global__ void fft_cols_k() {
    __shared__ float cre[16][129];
    __shared__ float cim[16][129];
    __shared__ float2 tws[128];
    int kb = blockIdx.x;                  // 0..8
    int c = blockIdx.y, b = blockIdx.z;
    int bc = b*Cn + c;
    int k0 = kb * 16;
    int ncols = (kb < 8) ? 16 : 1;
    int lg = (kb < 8) ? 4 : 0;
    int tid = threadIdx.x;                // 128
    tws[tid] = g_tw[tid];
    int kk = tid & 15, ht = tid >> 4;
    const float2* src = g_fft + (size_t)bc*Hn*WFn;
    for (int hb = 0; hb < 16; hb++) {
        int h = hb*8 + ht;
        if (kk < ncols) {
            float2 v = src[(size_t)h*WFn + k0 + kk];
            int j = __brev((unsigned)h) >> 25;
            cre[kk][j] = v.x; cim[kk][j] = v.y;
        }
    }
    __syncthreads();
    #pragma unroll
    for (int s = 1; s <= 7; s++) {
        int half = 1 << (s - 1);
        int total = ncols << 6;
        for (int e = tid; e < total; e += 128) {
            int col = e & (ncols - 1);
            int i = e >> lg;
            int off = i & (half - 1);
            int a = ((i >> (s - 1)) << s) + off;
            int bb = a + half;
            float2 tw = tws[off << (8 - s)];
            float br = cre[col][bb], bi = cim[col][bb];
            float ar = cre[col][a],  ai = cim[col][a];
            float xr = br*tw.x - bi*tw.y;
            float xi = br*tw.y + bi*tw.x;
            cre[col][a] = ar + xr; cim[col][a] = ai + xi;
            cre[col][bb] = ar - xr; cim[col][bb] = ai - xi;
        }
        __syncthreads();
    }
    const float sc = 0.0055242717280199026f;  // 1/sqrt(128*256)
    float* dst = g_mag + (size_t)bc*Hn*WFn;
    int total = ncols << 7;
    for (int e = tid; e < total; e += 128) {
        int col = e & (ncols - 1);
        int h = e >> lg;
        float r = cre[col][h], m = cim[col][h];
        dst[(size_t)h*WFn + k0 + col] = sqrtf(r*r + m*m) * sc;
    }
}

// mean over channels of g_mag -> out[b][h][k]
__global__ void chan_mean_k(float* __restrict__ out) {
    int h = blockIdx.x, b = blockIdx.y;
    for (int k = threadIdx.x; k < WFn; k += 160) {
        float s = 0.f;
        const float* p = g_mag + ((size_t)(b*Cn)*Hn + h)*WFn + k;
        #pragma unroll 4
        for (int c = 0; c < Cn; c++) s += p[(size_t)c*Hn*WFn];
        out[(size_t)(b*Hn + h)*WFn + k] = s * (1.f/Cn);
    }
}

// --------- fused freq branch: direct 49-tap separable stencil + pools -------
__global__ __launch_bounds__(512)
void freq_fused_k(const float* __restrict__ w7h, const float* __restrict__ b7h,
                  const float* __restrict__ w7w, const float* __restrict__ b7w) {
    extern __shared__ float A[];          // [128][132]
    __shared__ float S[4][132];
    __shared__ float bins[21];
    int c = blockIdx.x, b = blockIdx.y;
    int tid = threadIdx.x;
    const float* mp = g_mag + (size_t)(b*Cn + c)*Hn*WFn;
    for (int e = tid; e < 128*129; e += 512) {
        int h = e / 129, k = e - h*129;
        A[h*132 + k] = mp[e];
    }
    float wh[7], ww[7];
    #pragma unroll
    for (int d = 0; d < 7; d++) { wh[d] = w7h[c*7+d]; ww[d] = w7w[c*7+d]; }
    float bh = b7h[c], bw = b7w[c];
    __syncthreads();
    for (int t = tid; t < 4*129; t += 512) {
        int band = t / 129, k = t - band*129;
        float acc = 0.f;
        for (int hh = 0; hh < 32; hh++) {
            int h = band*32 + hh;
            float t2 = bw;
            #pragma unroll
            for (int d = 0; d < 7; d++) {
                int kk = k + d - 3;
                if (kk >= 0 && kk < 129) {
                    float t1 = bh;
                    #pragma unroll
                    for (int e = 0; e < 7; e++) {
                        int h2 = h + e - 3;
                        if (h2 >= 0 && h2 < 128) t1 += wh[e]*A[h2*132 + kk];
                    }
                    t2 += ww[d]*t1;
                }
            }
            acc += t2;
        }
        S[band][k] = acc;
    }
    __syncthreads();
    if (tid < 16) {
        int i = tid >> 2, j = tid & 3;
        int ws = (j*WFn)/4, we = ((j+1)*WFn + 3)/4;
        float s = 0;
        for (int k = ws; k < we; k++) s += S[i][k];
        bins[tid] = s / (32.f * (float)(we - ws));
    } else if (tid < 20) {
        int t2 = tid - 16; int i = t2 >> 1, j = t2 & 1;
        int ws = (j*WFn)/2, we = ((j+1)*WFn + 1)/2;
        float s = 0;
        for (int k = ws; k < we; k++) s += S[2*i][k] + S[2*i+1][k];
        bins[tid] = s / (64.f * (float)(we - ws));
    } else if (tid == 20) {
        float s = 0;
        for (int k = 0; k < WFn; k++) s += S[0][k]+S[1][k]+S[2][k]+S[3][k];
        bins[20] = s / (128.f*129.f);
    }
    __syncthreads();
    if (tid == 0) {
        float g2 = bins[16]+bins[17]+bins[18]+bins[19];
        float g3 = 0;
        for (int m = 0; m < 16; m++) g3 += bins[m];
        g_gvec[b*288 + c]        = bins[20];
        g_gvec[b*288 + Cn + c]   = g2 * 0.25f;
        g_gvec[b*288 + 2*Cn + c] = g3 * 0.0625f;
    }
}

// ------------------------- channel-attention MLP ----------------------------
__global__ void ca_mlp_k(const float* __restrict__ w1, const float* __restrict__ b1,
                         const float* __restrict__ w2, const float* __restrict__ b2) {
    __shared__ float gs[288], hs[MIDn];
    int b = blockIdx.x, tid = threadIdx.x;   // 96 threads
    for (int i = tid; i < 288; i += 96) gs[i] = g_gvec[b*288 + i];
    __syncthreads();
    if (tid < MIDn) {
        float a = b1[tid];
        for (int k = 0; k < 288; k++) a += w1[tid*288 + k]*gs[k];
        hs[tid] = fmaxf(a, 0.f);
    }
    __syncthreads();
    float a = b2[tid];
    #pragma unroll
    for (int m = 0; m < MIDn; m++) a += w2[tid*MIDn + m]*hs[m];
    g_ca[b*Cn + tid] = 1.f/(1.f + expf(-a));
}

// ------------------------- spatial branch -----------------------------------
__global__ void spatial_in_k(const float* __restrict__ x) {
    int h = blockIdx.x, b = blockIdx.y;
    int w = threadIdx.x;                  // 256
    int hw = h*Wn + w;
    const float* xp = x + (size_t)b*Cn*HWn + hw;
    float s = 0.f, s2 = 0.f;
    #pragma unroll 4
    for (int c = 0; c < Cn; c++) { float v = xp[(size_t)c*HWn]; s += v; s2 += v*v; }
    float mean = s * (1.f/Cn);
    float l2 = sqrtf(s2 * (1.f/Cn) + 1e-6f);
    float src = ((float)w + 0.5f)*(129.f/256.f) - 0.5f;
    float f0 = floorf(src); int i0 = (int)f0; float fr = src - f0;
    int ia = min(max(i0, 0), WFn-1), ib = min(max(i0+1, 0), WFn-1);
    const float* fp = g_fe + (size_t)(b*Hn + h)*WFn;
    float fv = fp[ia]*(1.f - fr) + fp[ib]*fr;
    g_s0[((size_t)(b*3+0))*HWn + hw] = mean;
    g_s0[((size_t)(b*3+1))*HWn + hw] = l2;
    g_s0[((size_t)(b*3+2))*HWn + hw] = fv;
}

// fused dwsp_h + dwsp_w + sr: one block per (h, b); 256 threads (w)
__global__ __launch_bounds__(256)
void sp_fused_k(const float* __restrict__ w15h, const float* __restrict__ b15h,
                const float* __restrict__ w15w, const float* __restrict__ b15w,
                const float* __restrict__ sr1w, const float* __restrict__ sr1b,
                const float* __restrict__ sr2w, const float* __restrict__ sr2b) {
    __shared__ float s1buf[3][3][272];
    __shared__ float sbuf[3][3][258];
    __shared__ float wsm[3][15], wsw[3][15];
    int h = blockIdx.x, b = blockIdx.y;
    int w = threadIdx.x;                 // 256
    if (w < 45) { wsm[w/15][w%15] = w15h[w]; wsw[w/15][w%15] = w15w[w]; }
    if (w < 7) {
        #pragma unroll
        for (int ch = 0; ch < 3; ch++)
            #pragma unroll
            for (int j = 0; j < 3; j++) { s1buf[ch][j][w] = 0.f; s1buf[ch][j][263+w] = 0.f; }
    }
    if (w < 9) {
        #pragma unroll
        for (int ch = 0; ch < 3; ch++)
            #pragma unroll
            for (int j = 0; j < 3; j++) s1buf[ch][j][263+w] = 0.f;
    }
    if (w < 3) {
        #pragma unroll
        for (int ch = 0; ch < 3; ch++) { sbuf[ch][w][0] = 0.f; sbuf[ch][w][257] = 0.f; }
    }
    __syncthreads();
    #pragma unroll
    for (int ch = 0; ch < 3; ch++) {
        const float* s0p = g_s0 + ((size_t)(b*3 + ch))*HWn + w;
        #pragma unroll
        for (int j = 0; j < 3; j++) {
            int hr = h + j - 1;
            float a = b15h[ch];
            #pragma unroll
            for (int d = 0; d < 15; d++) {
                int hh = hr + d - 7;
                if (hh >= 0 && hh < Hn) a += wsm[ch][d]*s0p[hh*Wn];
            }
            s1buf[ch][j][7 + w] = a;
        }
    }
    __syncthreads();
    #pragma unroll
    for (int ch = 0; ch < 3; ch++) {
        #pragma unroll
        for (int j = 0; j < 3; j++) {
            float a = b15w[ch];
            #pragma unroll
            for (int d = 0; d < 15; d++) a += wsw[ch][d]*s1buf[ch][j][w + d];
            sbuf[ch][j][1 + w] = a;
        }
    }
    __syncthreads();
    float acc = sr2b[0];
    #pragma unroll
    for (int ch = 0; ch < 3; ch++) {
        float v = sr1b[ch];
        #pragma unroll
        for (int ky = 0; ky < 3; ky++) {
            int hh = h + ky - 1; if (hh < 0 || hh >= Hn) continue;
            #pragma unroll
            for (int kx = 0; kx < 3; kx++) {
                v += sr1w[ch*9 + ky*3 + kx]*sbuf[ch][ky][w + kx];
            }
        }
        acc += sr2w[ch]*fmaxf(v, 0.f);
    }
    g_sa[(size_t)b*HWn + h*Wn + w] = 1.f/(1.f + expf(-acc));
}

__global__ void auxmisc_k() {
    int h = blockIdx.x, b = blockIdx.y;
    int w = threadIdx.x;                 // 256
    int hw = h*Wn + w;
    float theta = -3.14159265358979324f + (float)w * (6.2831853071795864f/255.f);
    float phi   = -1.57079632679489662f + (float)h * (3.14159265358979324f/127.f);
    size_t base = (size_t)b*AUXn*HWn + hw;
    g_aux[base + (size_t)96*HWn] = sinf(theta);
    g_aux[base + (size_t)97*HWn] = cosf(theta);
    g_aux[base + (size_t)98*HWn] = sinf(phi);
    g_aux[base + (size_t)99*HWn] = cosf(phi);
    float src = ((float)w + 0.5f)*(129.f/256.f) - 0.5f;
    float f0 = floorf(src); int i0 = (int)f0; float fr = src - f0;
    int ia = min(max(i0, 0), WFn-1), ib = min(max(i0+1, 0), WFn-1);
    const float* fp = g_fem + (size_t)(b*Hn + h)*WFn;
    g_aux[base + (size_t)100*HWn] = fp[ia]*(1.f - fr) + fp[ib]*fr;
}

// ------------- merged offset(18)+dg1(50) conv, pre-packed weights -----------
__global__ __launch_bounds__(256)
void convoffdg_k(const float* __restrict__ offbias,
                 const float* __restrict__ dg1b,
                 const float* __restrict__ dg2w, const float* __restrict__ dg2b) {
    constexpr int COUT = 68;
    constexpr int NO = 3;
    constexpr int CB = 8;
    __shared__ float2 tile2[CB][3][66];
    __shared__ float sgate[32][64];
    extern __shared__ float2 wdyn[];          // [CB][COUT*9]
    int bx = blockIdx.x;
    int seg = bx & 3; int h = (bx >> 2) & (Hn - 1); int b = bx >> 9;
    int w0 = seg * 64;
    int tid = threadIdx.x;
    int pg = tid & 7, og = tid >> 3;
    u64 pacc[NO][4];
    #pragma unroll
    for (int k = 0; k < NO; k++)
        #pragma unroll
        for (int q = 0; q < 4; q++) pacc[k][q] = 0ull;
    const float* inb = g_aux + (size_t)b*AUXn*HWn;
    int pv8idx = (pg == 7) ? 64 : (pg + 1);
    for (int c0 = 0; c0 < AUXn; c0 += CB) {
        for (int m = tid; m < CB*3*65; m += 256) {
            int ci = m / 195; int rem = m - ci*195; int r = rem / 65; int p = rem - r*65;
            int l = (p < 64) ? (((p & 7) << 3) | (p >> 3)) : 64;
            int hh = h + r - 1, ww = w0 + l - 1;
            float v0 = 0.f, v1 = 0.f;
            if (c0 + ci < AUXn && hh >= 0 && hh < Hn) {
                const float* rowp = inb + (size_t)(c0 + ci)*HWn + (size_t)hh*Wn;
                if (ww >= 0 && ww < Wn) v0 = rowp[ww];
                if (ww + 1 >= 0 && ww + 1 < Wn) v1 = rowp[ww + 1];
            }
            tile2[ci][r][p] = make_float2(v0, v1);
        }
        {   // coalesced float4 weight copy (pre-packed, incl. zero pad rows)
            const float4* wsrc = g_wpk68 + (size_t)c0*306;
            float4* wdst = (float4*)wdyn;
            for (int m = tid; m < CB*306; m += 256) wdst[m] = wsrc[m];
        }
        __syncthreads();
        #pragma unroll 2
        for (int ci = 0; ci < CB; ci++) {
            #pragma unroll
            for (int r = 0; r < 3; r++) {
                const float2* trow = tile2[ci][r];
                u64 pv[9];
                #pragma unroll
                for (int j = 0; j < 8; j++) pv[j] = *(const u64*)&trow[j*8 + pg];
                pv[8] = *(const u64*)&trow[pv8idx];
                #pragma unroll
                for (int k = 0; k < NO; k++) {
                    int o = og + 32*k;
                    if (o >= COUT) break;
                    const u64* wp = (const u64*)&wdyn[ci*(COUT*9) + o*9 + r*3];
                    u64 wb0 = wp[0], wb1 = wp[1], wb2 = wp[2];
                    #pragma unroll
                    for (int q = 0; q < 4; q++) {
                        pacc[k][q] = ffma2(wb0, pv[2*q],   pacc[k][q]);
                        pacc[k][q] = ffma2(wb1, pv[2*q+1], pacc[k][q]);
                        pacc[k][q] = ffma2(wb2, pv[2*q+2], pacc[k][q]);
                    }
                }
            }
        }
        __syncthreads();
    }
    float part[8];
    #pragma unroll
    for (int p = 0; p < 8; p++) part[p] = 0.f;
    #pragma unroll
    for (int k = 0; k < NO; k++) {
        int o = og + 32*k;
        if (o >= COUT) break;
        if (o < 18) {
            float bb = offbias[o];
            float* op = g_offb + ((size_t)(b*18 + o))*HWn + h*Wn + w0 + pg*8;
            #pragma unroll
            for (int q = 0; q < 4; q++) {
                float2 f = unpack2(pacc[k][q]);
                op[2*q] = f.x + bb; op[2*q+1] = f.y + bb;
            }
        } else {
            float bb = dg1b[o-18];
            float wv = dg2w[o-18];
            #pragma unroll
            for (int q = 0; q < 4; q++) {
                float2 f = unpack2(pacc[k][q]);
                part[2*q]   += wv * fmaxf(f.x + bb, 0.f);
                part[2*q+1] += wv * fmaxf(f.y + bb, 0.f);
            }
        }
    }
    #pragma unroll
    for (int p = 0; p < 8; p++) sgate[og][pg*8 + p] = part[p];
    __syncthreads();
    if (tid < 64) {
        float s = dg2b[0];
        #pragma unroll 8
        for (int o2 = 0; o2 < 32; o2++) s += sgate[o2][tid];
        g_gate[(size_t)b*HWn + h*Wn + w0 + tid] = 1.f/(1.f + expf(-s));
    }
}

// ------------- base 3x3 conv (96->96), pre-packed weights -------------------
__global__ __launch_bounds__(256)
void conv_base_k(const float* __restrict__ baseb) {
    constexpr int COUT = 96;
    constexpr int NO = 3;
    constexpr int CB = 8;
    __shared__ float2 tile2[CB][3][66];
    extern __shared__ float2 wdyn[];          // [CB][COUT*9]
    int bx = blockIdx.x;
    int seg = bx & 3; int h = (bx >> 2) & (Hn - 1); int b = bx >> 9;
    int w0 = seg * 64;
    int tid = threadIdx.x;
    int pg = tid & 7, og = tid >> 3;
    u64 pacc[NO][4];
    #pragma unroll
    for (int k = 0; k < NO; k++)
        #pragma unroll
        for (int q = 0; q < 4; q++) pacc[k][q] = 0ull;
    const float* inb = g_aux + (size_t)b*AUXn*HWn;
    int pv8idx = (pg == 7) ? 64 : (pg + 1);
    for (int c0 = 0; c0 < 96; c0 += CB) {
        for (int m = tid; m < CB*3*65; m += 256) {
            int ci = m / 195; int rem = m - ci*195; int r = rem / 65; int p = rem - r*65;
            int l = (p < 64) ? (((p & 7) << 3) | (p >> 3)) : 64;
            int hh = h + r - 1, ww = w0 + l - 1;
            float v0 = 0.f, v1 = 0.f;
            if (hh >= 0 && hh < Hn) {
                const float* rowp = inb + (size_t)(c0 + ci)*HWn + (size_t)hh*Wn;
                if (ww >= 0 && ww < Wn) v0 = rowp[ww];
                if (ww + 1 >= 0 && ww + 1 < Wn) v1 = rowp[ww + 1];
            }
            tile2[ci][r][p] = make_float2(v0, v1);
        }
        {
            const float4* wsrc = g_wpk96 + (size_t)c0*432;
            float4* wdst = (float4*)wdyn;
            for (int m = tid; m < CB*432; m += 256) wdst[m] = wsrc[m];
        }
        __syncthreads();
        #pragma unroll 2
        for (int ci = 0; ci < CB; ci++) {
            #pragma unroll
            for (int r = 0; r < 3; r++) {
                const float2* trow = tile2[ci][r];
                u64 pv[9];
                #pragma unroll
                for (int j = 0; j < 8; j++) pv[j] = *(const u64*)&trow[j*8 + pg];
                pv[8] = *(const u64*)&trow[pv8idx];
                #pragma unroll
                for (int k = 0; k < NO; k++) {
                    int o = og + 32*k;
                    const u64* wp = (const u64*)&wdyn[ci*(COUT*9) + o*9 + r*3];
                    u64 wb0 = wp[0], wb1 = wp[1], wb2 = wp[2];
                    #pragma unroll
                    for (int q = 0; q < 4; q++) {
                        pacc[k][q] = ffma2(wb0, pv[2*q],   pacc[k][q]);
                        pacc[k][q] = ffma2(wb1, pv[2*q+1], pacc[k][q]);
                        pacc[k][q] = ffma2(wb2, pv[2*q+2], pacc[k][q]);
                    }
                }
            }
        }
        __syncthreads();
    }
    #pragma unroll
    for (int k = 0; k < NO; k++) {
        int o = og + 32*k;
        float bb = baseb[o];
        float* op = g_ybase + ((size_t)(b*COUT + o))*HWn + h*Wn + w0 + pg*8;
        #pragma unroll
        for (int q = 0; q < 4; q++) {
            float2 f = unpack2(pacc[k][q]);
            op[2*q] = f.x + bb; op[2*q+1] = f.y + bb;
        }
    }
}

// ------------------------- deformable sampling + GEMM + combine -------------
__global__ __launch_bounds__(256)
void deform_combine_k(const float* __restrict__ defb) {
    extern __shared__ float dsm[];
    float2* samp2 = (float2*)dsm;                    // 2304 float2
    float2* wsh2  = (float2*)(dsm + 4608);           // 6912 float2
    float*  s_w   = dsm + 18432;                     // 2304
    int*    s_idx = (int*)(dsm + 20736);             // 2304
    int bx = blockIdx.x;
    int seg = bx & 3; int h = (bx >> 2) & (Hn - 1); int b = bx >> 9;
    int w0 = seg * 64;
    int tid = threadIdx.x;
    int pg = tid & 7, og = tid >> 3;

    for (int e = tid; e < 576; e += 256) {
        int t9 = e >> 6, p = e & 63;
        int wpx = w0 + p;
        size_t obase = ((size_t)b*18)*HWn + (size_t)h*Wn + wpx;
        float ox = g_offb[obase + (size_t)(2*t9)*HWn];
        float oy = g_offb[obase + (size_t)(2*t9+1)*HWn];
        float px = (float)wpx + ox;
        float py = (float)h + oy;
        float x0 = floorf(px), y0 = floorf(py);
        float fx = px - x0, fy = py - y0;
        #pragma unroll
        for (int j = 0; j < 4; j++) {
            float xj = x0 + (float)(j & 1);
            float yj = y0 + (float)(j >> 1);
            float valid = (xj >= 0.f && xj <= 255.f && yj >= 0.f && yj <= 127.f) ? 1.f : 0.f;
            float xc = fminf(fmaxf(xj, 0.f), 255.f);
            float yc = fminf(fmaxf(yj, 0.f), 127.f);
            s_idx[(t9*64 + p)*4 + j] = (int)yc * Wn + (int)xc;
            float wx = (j & 1) ? fx : (1.f - fx);
            float wy = (j >> 1) ? fy : (1.f - fy);
            s_w[(t9*64 + p)*4 + j] = wx * wy * valid;
        }
    }

    u64 pacc[3][4];
    #pragma unroll
    for (int k = 0; k < 3; k++)
        #pragma unroll
        for (int q = 0; q < 4; q++) pacc[k][q] = 0ull;

    for (int c0 = 0; c0 < 96; c0 += 8) {
        __syncthreads();
        for (int e = tid; e < 2304; e += 256) {
            int t9 = e >> 8; int rem = e & 255; int c = rem >> 5; int P = rem & 31;
            int p0 = 2*P;
            const float* yp = g_aux + ((size_t)(b*AUXn + c0 + c))*HWn;
            const int* i0 = &s_idx[(t9*64 + p0)*4];
            const float* q0 = &s_w[(t9*64 + p0)*4];
            float v0 = q0[0]*yp[i0[0]] + q0[1]*yp[i0[1]] + q0[2]*yp[i0[2]] + q0[3]*yp[i0[3]];
            const int* i1 = i0 + 4; const float* q1 = q0 + 4;
            float v1 = q1[0]*yp[i1[0]] + q1[1]*yp[i1[1]] + q1[2]*yp[i1[2]] + q1[3]*yp[i1[3]];
            samp2[(t9*8 + c)*32 + (((P & 3) << 3) | (P >> 2))] = make_float2(v0, v1);
        }
        {   // coalesced float4 weight copy from pre-packed dup table
            float4* wdst = (float4*)wsh2;
            for (int e4 = tid; e4 < 3456; e4 += 256) {
                int t9 = e4 / 384; int off4 = e4 - t9*384;
                wdst[e4] = g_defw2[(size_t)(t9*96 + c0)*48 + off4];
            }
        }
        __syncthreads();
        #pragma unroll 3
        for (int t9 = 0; t9 < 9; t9++) {
            #pragma unroll
            for (int c = 0; c < 8; c++) {
                const float2* sp = &samp2[(t9*8 + c)*32];
                u64 s0 = *(const u64*)&sp[0*8 + pg];
                u64 s1 = *(const u64*)&sp[1*8 + pg];
                u64 s2 = *(const u64*)&sp[2*8 + pg];
                u64 s3 = *(const u64*)&sp[3*8 + pg];
                const float2* wb = &wsh2[(t9*8 + c)*96];
                #pragma unroll
                for (int k = 0; k < 3; k++) {
                    u64 wp2 = *(const u64*)&wb[og + 32*k];
                    pacc[k][0] = ffma2(wp2, s0, pacc[k][0]);
                    pacc[k][1] = ffma2(wp2, s1, pacc[k][1]);
                    pacc[k][2] = ffma2(wp2, s2, pacc[k][2]);
                    pacc[k][3] = ffma2(wp2, s3, pacc[k][3]);
                }
            }
        }
    }
    #pragma unroll
    for (int k = 0; k < 3; k++) {
        int o = og + 32*k;
        float bb = defb[o];
        size_t rowoff = (size_t)h*Wn + w0 + pg*8;
        float* zp = g_z + ((size_t)(b*Cn + o))*HWn + rowoff;
        const float* yb = g_ybase + ((size_t)(b*Cn + o))*HWn + rowoff;
        const float* gp = g_gate + (size_t)b*HWn + rowoff;
        #pragma unroll
        for (int q = 0; q < 4; q++) {
            float2 f = unpack2(pacc[k][q]);
            float g0 = gp[2*q], g1 = gp[2*q+1];
            zp[2*q]   = (1.f - g0)*yb[2*q]   + g0*(f.x + bb);
            zp[2*q+1] = (1.f - g1)*yb[2*q+1] + g1*(f.y + bb);
        }
    }
}

// ------------------------- batchnorm (float4) -------------------------------
__global__ void bn_stats_k() {
    __shared__ float ss[256], ss2[256];
    int c = blockIdx.x, tid = threadIdx.x;
    float s = 0.f, s2 = 0.f;
    for (int b = 0; b < Bn; b++) {
        const float4* zp = (const float4*)(g_z + ((size_t)(b*Cn + c))*HWn);
        for (int i = tid; i < HWn/4; i += 256) {
            float4 v = zp[i];
            s += v.x + v.y + v.z + v.w;
            s2 += v.x*v.x + v.y*v.y + v.z*v.z + v.w*v.w;
        }
    }
    ss[tid] = s; ss2[tid] = s2;
    __syncthreads();
    for (int st = 128; st > 0; st >>= 1) {
        if (tid < st) { ss[tid] += ss[tid+st]; ss2[tid] += ss2[tid+st]; }
        __syncthreads();
    }
    if (tid == 0) {
        float inv = 1.f/(float)(Bn*HWn);
        float mu = ss[0]*inv;
        float var = ss2[0]*inv - mu*mu;
        g_mu[c] = mu;
        g_istd[c] = rsqrtf(var + 1e-5f);
    }
}

__global__ void bn_apply_k(const float* __restrict__ x,
                           const float* __restrict__ gam, const float* __restrict__ bet,
                           float* __restrict__ out) {
    int e = blockIdx.x*256 + threadIdx.x;
    int c = blockIdx.y, b = blockIdx.z;
    size_t i4 = ((size_t)(b*Cn + c))*(HWn/4) + e;
    float sc2 = g_istd[c]*gam[c];
    float sh = bet[c] - g_mu[c]*sc2;
    float4 z = ((const float4*)g_z)[i4];
    float4 xv = ((const float4*)x)[i4];
    float4 o;
    o.x = fmaxf(z.x*sc2 + sh + xv.x, 0.f);
    o.y = fmaxf(z.y*sc2 + sh + xv.y, 0.f);
    o.z = fmaxf(z.z*sc2 + sh + xv.z, 0.f);
    o.w = fmaxf(z.w*sc2 + sh + xv.w, 0.f);
    ((float4*)out)[i4] = o;
}

// ------------------------- launch -------------------------------------------
extern "C" void kernel_launch(void* const* d_in, const int* in_sizes, int n_in,
                              void* d_out, int out_size) {
    const float* x     = (const float*)d_in[0];
    const float* fdh_w = (const float*)d_in[1];
    const float* fdh_b = (const float*)d_in[2];
    const float* fdw_w = (const float*)d_in[3];
    const float* fdw_b = (const float*)d_in[4];
    const float* cp1_w = (const float*)d_in[5];
    const float* cp1_b = (const float*)d_in[6];
    const float* cp2_w = (const float*)d_in[7];
    const float* cp2_b = (const float*)d_in[8];
    const float* sdh_w = (const float*)d_in[9];
    const float* sdh_b = (const float*)d_in[10];
    const float* sdw_w = (const float*)d_in[11];
    const float* sdw_b = (const float*)d_in[12];
    const float* sr1_w = (const float*)d_in[13];
    const float* sr1_b = (const float*)d_in[14];
    const float* sr2_w = (const float*)d_in[15];
    const float* sr2_b = (const float*)d_in[16];
    const float* off_w = (const float*)d_in[17];
    const float* off_b = (const float*)d_in[18];
    const float* dg1_w = (const float*)d_in[19];
    const float* dg1_b = (const float*)d_in[20];
    const float* dg2_w = (const float*)d_in[21];
    const float* dg2_b = (const float*)d_in[22];
    const float* base_w = (const float*)d_in[23];
    const float* base_b = (const float*)d_in[24];
    const float* def_w = (const float*)d_in[25];
    const float* def_b = (const float*)d_in[26];
    const float* bn_g  = (const float*)d_in[27];
    const float* bn_b  = (const float*)d_in[28];
    float* out = (float*)d_out;

    float *p_fe, *p_fem;
    cudaGetSymbolAddress((void**)&p_fe, g_fe);
    cudaGetSymbolAddress((void**)&p_fem, g_fem);

    const int FREQ_SMEM = 128*132*4;         // 67584 B
    const int DEF_SMEM  = 23040 * 4;         // 92160 B
    const int C96_SMEM  = 8*96*9*8;          // 55296 B
    const int C68_SMEM  = 8*68*9*8;          // 39168 B
    cudaFuncSetAttribute(freq_fused_k, cudaFuncAttributeMaxDynamicSharedMemorySize, FREQ_SMEM);
    cudaFuncSetAttribute(deform_combine_k, cudaFuncAttributeMaxDynamicSharedMemorySize, DEF_SMEM);
    cudaFuncSetAttribute(conv_base_k, cudaFuncAttributeMaxDynamicSharedMemorySize, C96_SMEM);
    cudaFuncSetAttribute(convoffdg_k, cudaFuncAttributeMaxDynamicSharedMemorySize, C68_SMEM);

    bool fork = g_sync.ok;
    cudaStream_t sB = fork ? g_sync.s1 : 0;

    // ---- prep (single kernel) ----
    prep_all_k<<<CDIV(96*96*9,256), 256>>>(off_w, dg1_w, base_w, def_w);
    // ---- FFT(x) -> mag, fe ----
    fft_rows_k<<<dim3(Hn/2, Cn, Bn), 128>>>(x, Cn);
    fft_cols_k<<<dim3(9, Cn, Bn), 128>>>();
    chan_mean_k<<<dim3(Hn, Bn), 160>>>(p_fe);
    // ---- fork: spatial branch (sB) || freq branch (main) ----
    if (fork) {
        cudaEventRecord(g_sync.ev1, 0);
        cudaStreamWaitEvent(sB, g_sync.ev1, 0);
    }
    spatial_in_k<<<dim3(Hn, Bn), 256, 0, sB>>>(x);
    sp_fused_k<<<dim3(Hn, Bn), 256, 0, sB>>>(sdh_w, sdh_b, sdw_w, sdw_b,
                                             sr1_w, sr1_b, sr2_w, sr2_b);
    freq_fused_k<<<dim3(Cn, Bn), 512, FREQ_SMEM>>>(fdh_w, fdh_b, fdw_w, fdw_b);
    ca_mlp_k<<<Bn, 96>>>(cp1_w, cp1_b, cp2_w, cp2_b);
    if (fork) {
        cudaEventRecord(g_sync.evA, sB);
        cudaStreamWaitEvent(0, g_sync.evA, 0);
    }
    // ---- y = x*ca*sa (into aux) + FFT(y) rows, fused ----
    fft_rows_y_k<<<dim3(Hn/2, Cn, Bn), 128>>>(x);
    fft_cols_k<<<dim3(9, Cn, Bn), 128>>>();
    chan_mean_k<<<dim3(Hn, Bn), 160>>>(p_fem);
    auxmisc_k<<<dim3(Hn, Bn), 256>>>();
    // ---- fork: conv_base (sB) || convoffdg (main) ----
    if (fork) {
        cudaEventRecord(g_sync.ev2, 0);
        cudaStreamWaitEvent(sB, g_sync.ev2, 0);
    }
    conv_base_k<<<1024, 256, C96_SMEM, sB>>>(base_b);
    convoffdg_k<<<1024, 256, C68_SMEM>>>(off_b, dg1_b, dg2_w, dg2_b);
    if (fork) {
        cudaEventRecord(g_sync.evB, sB);
        cudaStreamWaitEvent(0, g_sync.evB, 0);
    }
    // ---- deformable ----
    deform_combine_k<<<1024, 256, DEF_SMEM>>>(def_b);
    // ---- BN + residual relu ----
    bn_stats_k<<<Cn, 256>>>();
    bn_apply_k<<<dim3(HWn/1024, Cn, Bn), 256>>>(x, bn_g, bn_b, out);
}

// round 13
// speedup vs baseline: 1.0497x; 1.0250x over previous
#include <cuda_runtime.h>
#include <math.h>

#define Bn 2
#define Cn 96
#define Hn 128
#define Wn 256
#define WFn 129
#define HWn (Hn*Wn)
#define AUXn 101
#define MIDn 24
#define DMIDn 50
#define NTOT (Bn*Cn*HWn)
#define NF (Bn*Cn*Hn*WFn)
#define CDIV(a,b) (((a)+(b)-1)/(b))

typedef unsigned long long u64;

__device__ __forceinline__ u64 ffma2(u64 a, u64 b, u64 c) {
    u64 d;
    asm("fma.rn.f32x2 %0, %1, %2, %3;" : "=l"(d) : "l"(a), "l"(b), "l"(c));
    return d;
}
__device__ __forceinline__ float2 unpack2(u64 v) {
    float2 d; asm("mov.b64 {%0, %1}, %2;" : "=f"(d.x), "=f"(d.y) : "l"(v)); return d;
}

// ------------------------- scratch (static device memory) -------------------
static __device__ float2 g_tw[128];
static __device__ float2 g_fft[(size_t)NF];
static __device__ float g_mag[NF];
static __device__ float g_fe[Bn*Hn*WFn];
static __device__ float g_fem[Bn*Hn*WFn];
static __device__ float g_gvec[Bn*3*Cn];
static __device__ float g_ca[Bn*Cn];
static __device__ float g_s0[Bn*3*HWn];
static __device__ float g_sa[Bn*HWn];
static __device__ float g_aux[(size_t)Bn*AUXn*HWn];
static __device__ float g_offb[Bn*18*HWn];
static __device__ float g_gate[Bn*HWn];
static __device__ float g_ybase[NTOT];
static __device__ float g_z[NTOT];
static __device__ float g_mu[Cn];
static __device__ float g_istd[Cn];
// pre-packed duplicated (w,w) weight tables (float4-aligned)
static __device__ float4 g_wpk68[31824];   // [104][68][9] float2
static __device__ float4 g_wpk96[41472];   // [96][96][9] float2
static __device__ float4 g_defw2[41472];   // [9][96][96] float2

// ------------------------- stream/event infra (static init) -----------------
struct SyncInfra {
    cudaStream_t s1;
    cudaEvent_t ev1, evA, ev2, evB;
    bool ok;
    SyncInfra() {
        ok = true;
        if (cudaStreamCreateWithFlags(&s1, cudaStreamNonBlocking) != cudaSuccess) { ok = false; s1 = 0; return; }
        if (cudaEventCreateWithFlags(&ev1, cudaEventDisableTiming) != cudaSuccess) { ok = false; return; }
        if (cudaEventCreateWithFlags(&evA, cudaEventDisableTiming) != cudaSuccess) { ok = false; return; }
        if (cudaEventCreateWithFlags(&ev2, cudaEventDisableTiming) != cudaSuccess) { ok = false; return; }
        if (cudaEventCreateWithFlags(&evB, cudaEventDisableTiming) != cudaSuccess) { ok = false; return; }
    }
};
static SyncInfra g_sync;

// ------------------------- merged prep kernel --------------------------------
__global__ void prep_all_k(const float* __restrict__ offw, const float* __restrict__ dg1w,
                           const float* __restrict__ basew, const float* __restrict__ defw) {
    int i = blockIdx.x*256 + threadIdx.x;
    if (i < 128) {
        float ang = -6.2831853071795864f * (float)i / 256.f;
        float s, c; sincosf(ang, &s, &c);
        g_tw[i] = make_float2(c, s);
    }
    if (i < 104*68*9) {
        int ci = i / 612; int rem = i - ci*612; int o = rem / 9; int j = rem - o*9;
        float v = 0.f;
        if (ci < AUXn) {
            if (o < 18) v = offw[((size_t)o*AUXn + ci)*9 + j];
            else        v = dg1w[((size_t)(o-18)*AUXn + ci)*9 + j];
        }
        ((float2*)g_wpk68)[i] = make_float2(v, v);
    }
    if (i < 96*96*9) {
        int ci = i / 864; int rem = i - ci*864; int o = rem / 9; int j = rem - o*9;
        float v = basew[((size_t)o*96 + ci)*9 + j];
        ((float2*)g_wpk96)[i] = make_float2(v, v);
        int o2 = i % 96; int c2 = (i / 96) % 96; int t2 = i / (96*96);
        float v2 = defw[((size_t)o2*96 + c2)*9 + t2];
        ((float2*)g_defw2)[i] = make_float2(v2, v2);
    }
}

// ------------------------- FFT kernels (split, high-parallel) ---------------
__global__ void fft_rows_k(const float* __restrict__ in, int cstride) {
    __shared__ float re[256], im[256];
    __shared__ float2 tws[128];
    int h0 = blockIdx.x * 2;
    int c = blockIdx.y, b = blockIdx.z;
    const float* r0 = in + ((size_t)(b*cstride + c)*Hn + h0)*Wn;
    const float* r1 = r0 + Wn;
    int tid = threadIdx.x;                // 128
    tws[tid] = g_tw[tid];
    for (int i = tid; i < 256; i += 128) {
        int j = __brev((unsigned)i) >> 24;
        re[j] = r0[i];
        im[j] = r1[i];
    }
    __syncthreads();
    #pragma unroll
    for (int s = 1; s <= 8; s++) {
        int half = 1 << (s - 1);
        int i = tid;
        int off = i & (half - 1);
        int a = ((i >> (s - 1)) << s) + off;
        int bb = a + half;
        float2 tw = tws[off << (8 - s)];
        float br = re[bb], bi = im[bb];
        float ar = re[a],  ai = im[a];
        float xr = br*tw.x - bi*tw.y;
        float xi = br*tw.y + bi*tw.x;
        re[a] = ar + xr; im[a] = ai + xi;
        re[bb] = ar - xr; im[bb] = ai - xi;
        __syncthreads();
    }
    float2* out0 = g_fft + ((size_t)(b*Cn + c)*Hn + h0)*WFn;
    float2* out1 = out0 + WFn;
    int k = tid;
    float zr = re[k], zi = im[k];
    int km = (256 - k) & 255;
    float wr = re[km], wi = im[km];
    out0[k] = make_float2(0.5f*(zr + wr), 0.5f*(zi - wi));
    out1[k] = make_float2(0.5f*(zi + wi), -0.5f*(zr - wr));
    if (tid == 0) {
        out0[128] = make_float2(re[128], 0.f);
        out1[128] = make_float2(im[128], 0.f);
    }
}

// fused: y = x*ca*sa (written to g_aux) + row FFT of y
__global__ void fft_rows_y_k(const float* __restrict__ x) {
    __shared__ float re[256], im[256];
    __shared__ float2 tws[128];
    int h0 = blockIdx.x * 2;
    int c = blockIdx.y, b = blockIdx.z;
    const float* r0 = x + ((size_t)(b*Cn + c)*Hn + h0)*Wn;
    const float* r1 = r0 + Wn;
    float* y0 = g_aux + ((size_t)(b*AUXn + c)*Hn + h0)*Wn;
    float* y1 = y0 + Wn;
    const float* sa0 = g_sa + (size_t)b*HWn + h0*Wn;
    const float* sa1 = sa0 + Wn;
    float cav = g_ca[b*Cn + c];
    int tid = threadIdx.x;                // 128
    tws[tid] = g_tw[tid];
    for (int i = tid; i < 256; i += 128) {
        int j = __brev((unsigned)i) >> 24;
        float v0 = r0[i]*cav*sa0[i];
        float v1 = r1[i]*cav*sa1[i];
        y0[i] = v0; y1[i] = v1;
        re[j] = v0;
        im[j] = v1;
    }
    __syncthreads();
    #pragma unroll
    for (int s = 1; s <= 8; s++) {
        int half = 1 << (s - 1);
        int i = tid;
        int off = i & (half - 1);
        int a = ((i >> (s - 1)) << s) + off;
        int bb = a + half;
        float2 tw = tws[off << (8 - s)];
        float br = re[bb], bi = im[bb];
        float ar = re[a],  ai = im[a];
        float xr = br*tw.x - bi*tw.y;
        float xi = br*tw.y + bi*tw.x;
        re[a] = ar + xr; im[a] = ai + xi;
        re[bb] = ar - xr; im[bb] = ai - xi;
        __syncthreads();
    }
    float2* out0 = g_fft + ((size_t)(b*Cn + c)*Hn + h0)*WFn;
    float2* out1 = out0 + WFn;
    int k = tid;
    float zr = re[k], zi = im[k];
    int km = (256 - k) & 255;
    float wr = re[km], wi = im[km];
    out0[k] = make_float2(0.5f*(zr + wr), 0.5f*(zi - wi));
    out1[k] = make_float2(0.5f*(zi + wi), -0.5f*(zr - wr));
    if (tid == 0) {
        out0[128] = make_float2(re[128], 0.f);
        out1[128] = make_float2(im[128], 0.f);
    }
}

// 128-pt FFT down columns, 16 columns per block (coalesced), |.| * 1/sqrt(HW)
__global__ void fft_cols_k() {
    __shared__ float cre[16][129];
    __shared__ float cim[16][129];
    __shared__ float2 tws[128];
    int kb = blockIdx.x;                  // 0..8
    int c = blockIdx.y, b = blockIdx.z;
    int bc = b*Cn + c;
    int k0 = kb * 16;
    int ncols = (kb < 8) ? 16 : 1;
    int lg = (kb < 8) ? 4 : 0;
    int tid = threadIdx.x;                // 128
    tws[tid] = g_tw[tid];
    int kk = tid & 15, ht = tid >> 4;
    const float2* src = g_fft + (size_t)bc*Hn*WFn;
    for (int hb = 0; hb < 16; hb++) {
        int h = hb*8 + ht;
        if (kk < ncols) {
            float2 v = src[(size_t)h*WFn + k0 + kk];
            int j = __brev((unsigned)h) >> 25;
            cre[kk][j] = v.x; cim[kk][j] = v.y;
        }
    }
    __syncthreads();
    #pragma unroll
    for (int s = 1; s <= 7; s++) {
        int half = 1 << (s - 1);
        int total = ncols << 6;
        for (int e = tid; e < total; e += 128) {
            int col = e & (ncols - 1);
            int i = e >> lg;
            int off = i & (half - 1);
            int a = ((i >> (s - 1)) << s) + off;
            int bb = a + half;
            float2 tw = tws[off << (8 - s)];
            float br = cre[col][bb], bi = cim[col][bb];
            float ar = cre[col][a],  ai = cim[col][a];
            float xr = br*tw.x - bi*tw.y;
            float xi = br*tw.y + bi*tw.x;
            cre[col][a] = ar + xr; cim[col][a] = ai + xi;
            cre[col][bb] = ar - xr; cim[col][bb] = ai - xi;
        }
        __syncthreads();
    }
    const float sc = 0.0055242717280199026f;  // 1/sqrt(128*256)
    float* dst = g_mag + (size_t)bc*Hn*WFn;
    int total = ncols << 7;
    for (int e = tid; e < total; e += 128) {
        int col = e & (ncols - 1);
        int h = e >> lg;
        float r = cre[col][h], m = cim[col][h];
        dst[(size_t)h*WFn + k0 + col] = sqrtf(r*r + m*m) * sc;
    }
}

// mean over channels of g_mag -> out[b][h][k] (4-way channel-parallel)
__global__ __launch_bounds__(512)
void chan_mean_k(float* __restrict__ out) {
    __shared__ float part[4][132];
    int h = blockIdx.x, b = blockIdx.y;
    int tid = threadIdx.x;                // 512
    int cg = tid >> 7, lk = tid & 127;
    const float* p0 = g_mag + ((size_t)(b*Cn + cg*24)*Hn + h)*WFn;
    for (int k = lk; k < WFn; k += 128) {
        float s = 0.f;
        #pragma unroll 6
        for (int c = 0; c < 24; c++) s += p0[(size_t)c*Hn*WFn + k];
        part[cg][k] = s;
    }
    __syncthreads();
    if (tid < WFn) {
        float s = part[0][tid] + part[1][tid] + part[2][tid] + part[3][tid];
        out[(size_t)(b*Hn + h)*WFn + tid] = s * (1.f/Cn);
    }
}

// --------- fused freq branch: direct 49-tap separable stencil + pools -------
__global__ __launch_bounds__(512)
void freq_fused_k(const float* __restrict__ w7h, const float* __restrict__ b7h,
                  const float* __restrict__ w7w, const float* __restrict__ b7w) {
    extern __shared__ float A[];          // [128][132]
    __shared__ float S[4][132];
    __shared__ float bins[21];
    int c = blockIdx.x, b = blockIdx.y;
    int tid = threadIdx.x;
    const float* mp = g_mag + (size_t)(b*Cn + c)*Hn*WFn;
    for (int e = tid; e < 128*129; e += 512) {
        int h = e / 129, k = e - h*129;
        A[h*132 + k] = mp[e];
    }
    float wh[7], ww[7];
    #pragma unroll
    for (int d = 0; d < 7; d++) { wh[d] = w7h[c*7+d]; ww[d] = w7w[c*7+d]; }
    float bh = b7h[c], bw = b7w[c];
    __syncthreads();
    for (int t = tid; t < 4*129; t += 512) {
        int band = t / 129, k = t - band*129;
        float acc = 0.f;
        for (int hh = 0; hh < 32; hh++) {
            int h = band*32 + hh;
            float t2 = bw;
            #pragma unroll
            for (int d = 0; d < 7; d++) {
                int kk = k + d - 3;
                if (kk >= 0 && kk < 129) {
                    float t1 = bh;
                    #pragma unroll
                    for (int e = 0; e < 7; e++) {
                        int h2 = h + e - 3;
                        if (h2 >= 0 && h2 < 128) t1 += wh[e]*A[h2*132 + kk];
                    }
                    t2 += ww[d]*t1;
                }
            }
            acc += t2;
        }
        S[band][k] = acc;
    }
    __syncthreads();
    if (tid < 16) {
        int i = tid >> 2, j = tid & 3;
        int ws = (j*WFn)/4, we = ((j+1)*WFn + 3)/4;
        float s = 0;
        for (int k = ws; k < we; k++) s += S[i][k];
        bins[tid] = s / (32.f * (float)(we - ws));
    } else if (tid < 20) {
        int t2 = tid - 16; int i = t2 >> 1, j = t2 & 1;
        int ws = (j*WFn)/2, we = ((j+1)*WFn + 1)/2;
        float s = 0;
        for (int k = ws; k < we; k++) s += S[2*i][k] + S[2*i+1][k];
        bins[tid] = s / (64.f * (float)(we - ws));
    } else if (tid == 20) {
        float s = 0;
        for (int k = 0; k < WFn; k++) s += S[0][k]+S[1][k]+S[2][k]+S[3][k];
        bins[20] = s / (128.f*129.f);
    }
    __syncthreads();
    if (tid == 0) {
        float g2 = bins[16]+bins[17]+bins[18]+bins[19];
        float g3 = 0;
        for (int m = 0; m < 16; m++) g3 += bins[m];
        g_gvec[b*288 + c]        = bins[20];
        g_gvec[b*288 + Cn + c]   = g2 * 0.25f;
        g_gvec[b*288 + 2*Cn + c] = g3 * 0.0625f;
    }
}

// ------------------------- channel-attention MLP ----------------------------
__global__ void ca_mlp_k(const float* __restrict__ w1, const float* __restrict__ b1,
                         const float* __restrict__ w2, const float* __restrict__ b2) {
    __shared__ float gs[288], hs[MIDn];
    int b = blockIdx.x, tid = threadIdx.x;   // 96 threads
    for (int i = tid; i < 288; i += 96) gs[i] = g_gvec[b*288 + i];
    __syncthreads();
    if (tid < MIDn) {
        float a = b1[tid];
        for (int k = 0; k < 288; k++) a += w1[tid*288 + k]*gs[k];
        hs[tid] = fmaxf(a, 0.f);
    }
    __syncthreads();
    float a = b2[tid];
    #pragma unroll
    for (int m = 0; m < MIDn; m++) a += w2[tid*MIDn + m]*hs[m];
    g_ca[b*Cn + tid] = 1.f/(1.f + expf(-a));
}

// ------------------------- spatial branch -----------------------------------
__global__ void spatial_in_k(const float* __restrict__ x) {
    int h = blockIdx.x, b = blockIdx.y;
    int w = threadIdx.x;                  // 256
    int hw = h*Wn + w;
    const float* xp = x + (size_t)b*Cn*HWn + hw;
    float s = 0.f, s2 = 0.f;
    #pragma unroll 4
    for (int c = 0; c < Cn; c++) { float v = xp[(size_t)c*HWn]; s += v; s2 += v*v; }
    float mean = s * (1.f/Cn);
    float l2 = sqrtf(s2 * (1.f/Cn) + 1e-6f);
    float src = ((float)w + 0.5f)*(129.f/256.f) - 0.5f;
    float f0 = floorf(src); int i0 = (int)f0; float fr = src - f0;
    int ia = min(max(i0, 0), WFn-1), ib = min(max(i0+1, 0), WFn-1);
    const float* fp = g_fe + (size_t)(b*Hn + h)*WFn;
    float fv = fp[ia]*(1.f - fr) + fp[ib]*fr;
    g_s0[((size_t)(b*3+0))*HWn + hw] = mean;
    g_s0[((size_t)(b*3+1))*HWn + hw] = l2;
    g_s0[((size_t)(b*3+2))*HWn + hw] = fv;
}

// fused dwsp_h + dwsp_w + sr: one block per (h, b); 256 threads (w)
__global__ __launch_bounds__(256)
void sp_fused_k(const float* __restrict__ w15h, const float* __restrict__ b15h,
                const float* __restrict__ w15w, const float* __restrict__ b15w,
                const float* __restrict__ sr1w, const float* __restrict__ sr1b,
                const float* __restrict__ sr2w, const float* __restrict__ sr2b) {
    __shared__ float s1buf[3][3][272];
    __shared__ float sbuf[3][3][258];
    __shared__ float wsm[3][15], wsw[3][15];
    int h = blockIdx.x, b = blockIdx.y;
    int w = threadIdx.x;                 // 256
    if (w < 45) { wsm[w/15][w%15] = w15h[w]; wsw[w/15][w%15] = w15w[w]; }
    if (w < 7) {
        #pragma unroll
        for (int ch = 0; ch < 3; ch++)
            #pragma unroll
            for (int j = 0; j < 3; j++) { s1buf[ch][j][w] = 0.f; s1buf[ch][j][263+w] = 0.f; }
    }
    if (w < 9) {
        #pragma unroll
        for (int ch = 0; ch < 3; ch++)
            #pragma unroll
            for (int j = 0; j < 3; j++) s1buf[ch][j][263+w] = 0.f;
    }
    if (w < 3) {
        #pragma unroll
        for (int ch = 0; ch < 3; ch++) { sbuf[ch][w][0] = 0.f; sbuf[ch][w][257] = 0.f; }
    }
    __syncthreads();
    #pragma unroll
    for (int ch = 0; ch < 3; ch++) {
        const float* s0p = g_s0 + ((size_t)(b*3 + ch))*HWn + w;
        #pragma unroll
        for (int j = 0; j < 3; j++) {
            int hr = h + j - 1;
            float a = b15h[ch];
            #pragma unroll
            for (int d = 0; d < 15; d++) {
                int hh = hr + d - 7;
                if (hh >= 0 && hh < Hn) a += wsm[ch][d]*s0p[hh*Wn];
            }
            s1buf[ch][j][7 + w] = a;
        }
    }
    __syncthreads();
    #pragma unroll
    for (int ch = 0; ch < 3; ch++) {
        #pragma unroll
        for (int j = 0; j < 3; j++) {
            float a = b15w[ch];
            #pragma unroll
            for (int d = 0; d < 15; d++) a += wsw[ch][d]*s1buf[ch][j][w + d];
            sbuf[ch][j][1 + w] = a;
        }
    }
    __syncthreads();
    float acc = sr2b[0];
    #pragma unroll
    for (int ch = 0; ch < 3; ch++) {
        float v = sr1b[ch];
        #pragma unroll
        for (int ky = 0; ky < 3; ky++) {
            int hh = h + ky - 1; if (hh < 0 || hh >= Hn) continue;
            #pragma unroll
            for (int kx = 0; kx < 3; kx++) {
                v += sr1w[ch*9 + ky*3 + kx]*sbuf[ch][ky][w + kx];
            }
        }
        acc += sr2w[ch]*fmaxf(v, 0.f);
    }
    g_sa[(size_t)b*HWn + h*Wn + w] = 1.f/(1.f + expf(-acc));
}

__global__ void auxmisc_k() {
    int h = blockIdx.x, b = blockIdx.y;
    int w = threadIdx.x;                 // 256
    int hw = h*Wn + w;
    float theta = -3.14159265358979324f + (float)w * (6.2831853071795864f/255.f);
    float phi   = -1.57079632679489662f + (float)h * (3.14159265358979324f/127.f);
    size_t base = (size_t)b*AUXn*HWn + hw;
    g_aux[base + (size_t)96*HWn] = sinf(theta);
    g_aux[base + (size_t)97*HWn] = cosf(theta);
    g_aux[base + (size_t)98*HWn] = sinf(phi);
    g_aux[base + (size_t)99*HWn] = cosf(phi);
    float src = ((float)w + 0.5f)*(129.f/256.f) - 0.5f;
    float f0 = floorf(src); int i0 = (int)f0; float fr = src - f0;
    int ia = min(max(i0, 0), WFn-1), ib = min(max(i0+1, 0), WFn-1);
    const float* fp = g_fem + (size_t)(b*Hn + h)*WFn;
    g_aux[base + (size_t)100*HWn] = fp[ia]*(1.f - fr) + fp[ib]*fr;
}

// ------------- merged offset(18)+dg1(50) conv, pre-packed weights -----------
__global__ __launch_bounds__(256)
void convoffdg_k(const float* __restrict__ offbias,
                 const float* __restrict__ dg1b,
                 const float* __restrict__ dg2w, const float* __restrict__ dg2b) {
    constexpr int COUT = 68;
    constexpr int NO = 3;
    constexpr int CB = 8;
    __shared__ float2 tile2[CB][3][66];
    __shared__ float sgate[32][64];
    extern __shared__ float2 wdyn[];          // [CB][COUT*9]
    int bx = blockIdx.x;
    int seg = bx & 3; int h = (bx >> 2) & (Hn - 1); int b = bx >> 9;
    int w0 = seg * 64;
    int tid = threadIdx.x;
    int pg = tid & 7, og = tid >> 3;
    u64 pacc[NO][4];
    #pragma unroll
    for (int k = 0; k < NO; k++)
        #pragma unroll
        for (int q = 0; q < 4; q++) pacc[k][q] = 0ull;
    const float* inb = g_aux + (size_t)b*AUXn*HWn;
    int pv8idx = (pg == 7) ? 64 : (pg + 1);
    for (int c0 = 0; c0 < AUXn; c0 += CB) {
        for (int m = tid; m < CB*3*65; m += 256) {
            int ci = m / 195; int rem = m - ci*195; int r = rem / 65; int p = rem - r*65;
            int l = (p < 64) ? (((p & 7) << 3) | (p >> 3)) : 64;
            int hh = h + r - 1, ww = w0 + l - 1;
            float v0 = 0.f, v1 = 0.f;
            if (c0 + ci < AUXn && hh >= 0 && hh < Hn) {
                const float* rowp = inb + (size_t)(c0 + ci)*HWn + (size_t)hh*Wn;
                if (ww >= 0 && ww < Wn) v0 = rowp[ww];
                if (ww + 1 >= 0 && ww + 1 < Wn) v1 = rowp[ww + 1];
            }
            tile2[ci][r][p] = make_float2(v0, v1);
        }
        {
            const float4* wsrc = g_wpk68 + (size_t)c0*306;
            float4* wdst = (float4*)wdyn;
            for (int m = tid; m < CB*306; m += 256) wdst[m] = wsrc[m];
        }
        __syncthreads();
        #pragma unroll 2
        for (int ci = 0; ci < CB; ci++) {
            #pragma unroll
            for (int r = 0; r < 3; r++) {
                const float2* trow = tile2[ci][r];
                u64 pv[9];
                #pragma unroll
                for (int j = 0; j < 8; j++) pv[j] = *(const u64*)&trow[j*8 + pg];
                pv[8] = *(const u64*)&trow[pv8idx];
                #pragma unroll
                for (int k = 0; k < NO; k++) {
                    int o = og + 32*k;
                    if (o >= COUT) break;
                    const u64* wp = (const u64*)&wdyn[ci*(COUT*9) + o*9 + r*3];
                    u64 wb0 = wp[0], wb1 = wp[1], wb2 = wp[2];
                    #pragma unroll
                    for (int q = 0; q < 4; q++) {
                        pacc[k][q] = ffma2(wb0, pv[2*q],   pacc[k][q]);
                        pacc[k][q] = ffma2(wb1, pv[2*q+1], pacc[k][q]);
                        pacc[k][q] = ffma2(wb2, pv[2*q+2], pacc[k][q]);
                    }
                }
            }
        }
        __syncthreads();
    }
    float part[8];
    #pragma unroll
    for (int p = 0; p < 8; p++) part[p] = 0.f;
    #pragma unroll
    for (int k = 0; k < NO; k++) {
        int o = og + 32*k;
        if (o >= COUT) break;
        if (o < 18) {
            float bb = offbias[o];
            float* op = g_offb + ((size_t)(b*18 + o))*HWn + h*Wn + w0 + pg*8;
            #pragma unroll
            for (int q = 0; q < 4; q++) {
                float2 f = unpack2(pacc[k][q]);
                op[2*q] = f.x + bb; op[2*q+1] = f.y + bb;
            }
        } else {
            float bb = dg1b[o-18];
            float wv = dg2w[o-18];
            #pragma unroll
            for (int q = 0; q < 4; q++) {
                float2 f = unpack2(pacc[k][q]);
                part[2*q]   += wv * fmaxf(f.x + bb, 0.f);
                part[2*q+1] += wv * fmaxf(f.y + bb, 0.f);
            }
        }
    }
    #pragma unroll
    for (int p = 0; p < 8; p++) sgate[og][pg*8 + p] = part[p];
    __syncthreads();
    if (tid < 64) {
        float s = dg2b[0];
        #pragma unroll 8
        for (int o2 = 0; o2 < 32; o2++) s += sgate[o2][tid];
        g_gate[(size_t)b*HWn + h*Wn + w0 + tid] = 1.f/(1.f + expf(-s));
    }
}

// ------------- base 3x3 conv (96->96), pre-packed weights -------------------
__global__ __launch_bounds__(256)
void conv_base_k(const float* __restrict__ baseb) {
    constexpr int COUT = 96;
    constexpr int NO = 3;
    constexpr int CB = 8;
    __shared__ float2 tile2[CB][3][66];
    extern __shared__ float2 wdyn[];          // [CB][COUT*9]
    int bx = blockIdx.x;
    int seg = bx & 3; int h = (bx >> 2) & (Hn - 1); int b = bx >> 9;
    int w0 = seg * 64;
    int tid = threadIdx.x;
    int pg = tid & 7, og = tid >> 3;
    u64 pacc[NO][4];
    #pragma unroll
    for (int k = 0; k < NO; k++)
        #pragma unroll
        for (int q = 0; q < 4; q++) pacc[k][q] = 0ull;
    const float* inb = g_aux + (size_t)b*AUXn*HWn;
    int pv8idx = (pg == 7) ? 64 : (pg + 1);
    for (int c0 = 0; c0 < 96; c0 += CB) {
        for (int m = tid; m < CB*3*65; m += 256) {
            int ci = m / 195; int rem = m - ci*195; int r = rem / 65; int p = rem - r*65;
            int l = (p < 64) ? (((p & 7) << 3) | (p >> 3)) : 64;
            int hh = h + r - 1, ww = w0 + l - 1;
            float v0 = 0.f, v1 = 0.f;
            if (hh >= 0 && hh < Hn) {
                const float* rowp = inb + (size_t)(c0 + ci)*HWn + (size_t)hh*Wn;
                if (ww >= 0 && ww < Wn) v0 = rowp[ww];
                if (ww + 1 >= 0 && ww + 1 < Wn) v1 = rowp[ww + 1];
            }
            tile2[ci][r][p] = make_float2(v0, v1);
        }
        {
            const float4* wsrc = g_wpk96 + (size_t)c0*432;
            float4* wdst = (float4*)wdyn;
            for (int m = tid; m < CB*432; m += 256) wdst[m] = wsrc[m];
        }
        __syncthreads();
        #pragma unroll 2
        for (int ci = 0; ci < CB; ci++) {
            #pragma unroll
            for (int r = 0; r < 3; r++) {
                const float2* trow = tile2[ci][r];
                u64 pv[9];
                #pragma unroll
                for (int j = 0; j < 8; j++) pv[j] = *(const u64*)&trow[j*8 + pg];
                pv[8] = *(const u64*)&trow[pv8idx];
                #pragma unroll
                for (int k = 0; k < NO; k++) {
                    int o = og + 32*k;
                    const u64* wp = (const u64*)&wdyn[ci*(COUT*9) + o*9 + r*3];
                    u64 wb0 = wp[0], wb1 = wp[1], wb2 = wp[2];
                    #pragma unroll
                    for (int q = 0; q < 4; q++) {
                        pacc[k][q] = ffma2(wb0, pv[2*q],   pacc[k][q]);
                        pacc[k][q] = ffma2(wb1, pv[2*q+1], pacc[k][q]);
                        pacc[k][q] = ffma2(wb2, pv[2*q+2], pacc[k][q]);
                    }
                }
            }
        }
        __syncthreads();
    }
    #pragma unroll
    for (int k = 0; k < NO; k++) {
        int o = og + 32*k;
        float bb = baseb[o];
        float* op = g_ybase + ((size_t)(b*COUT + o))*HWn + h*Wn + w0 + pg*8;
        #pragma unroll
        for (int q = 0; q < 4; q++) {
            float2 f = unpack2(pacc[k][q]);
            op[2*q] = f.x + bb; op[2*q+1] = f.y + bb;
        }
    }
}

// ------------------------- deformable sampling + GEMM + combine -------------
__global__ __launch_bounds__(256)
void deform_combine_k(const float* __restrict__ defb) {
    extern __shared__ float dsm[];
    float2* samp2 = (float2*)dsm;                    // 2304 float2
    float2* wsh2  = (float2*)(dsm + 4608);           // 6912 float2
    float*  s_w   = dsm + 18432;                     // 2304
    int*    s_idx = (int*)(dsm + 20736);             // 2304
    int bx = blockIdx.x;
    int seg = bx & 3; int h = (bx >> 2) & (Hn - 1); int b = bx >> 9;
    int w0 = seg * 64;
    int tid = threadIdx.x;
    int pg = tid & 7, og = tid >> 3;

    for (int e = tid; e < 576; e += 256) {
        int t9 = e >> 6, p = e & 63;
        int wpx = w0 + p;
        size_t obase = ((size_t)b*18)*HWn + (size_t)h*Wn + wpx;
        float ox = g_offb[obase + (size_t)(2*t9)*HWn];
        float oy = g_offb[obase + (size_t)(2*t9+1)*HWn];
        float px = (float)wpx + ox;
        float py = (float)h + oy;
        float x0 = floorf(px), y0 = floorf(py);
        float fx = px - x0, fy = py - y0;
        #pragma unroll
        for (int j = 0; j < 4; j++) {
            float xj = x0 + (float)(j & 1);
            float yj = y0 + (float)(j >> 1);
            float valid = (xj >= 0.f && xj <= 255.f && yj >= 0.f && yj <= 127.f) ? 1.f : 0.f;
            float xc = fminf(fmaxf(xj, 0.f), 255.f);
            float yc = fminf(fmaxf(yj, 0.f), 127.f);
            s_idx[(t9*64 + p)*4 + j] = (int)yc * Wn + (int)xc;
            float wx = (j & 1) ? fx : (1.f - fx);
            float wy = (j >> 1) ? fy : (1.f - fy);
            s_w[(t9*64 + p)*4 + j] = wx * wy * valid;
        }
    }

    u64 pacc[3][4];
    #pragma unroll
    for (int k = 0; k < 3; k++)
        #pragma unroll
        for (int q = 0; q < 4; q++) pacc[k][q] = 0ull;

    for (int c0 = 0; c0 < 96; c0 += 8) {
        __syncthreads();
        for (int e = tid; e < 2304; e += 256) {
            int t9 = e >> 8; int rem = e & 255; int c = rem >> 5; int P = rem & 31;
            int p0 = 2*P;
            const float* yp = g_aux + ((size_t)(b*AUXn + c0 + c))*HWn;
            const int* i0 = &s_idx[(t9*64 + p0)*4];
            const float* q0 = &s_w[(t9*64 + p0)*4];
            float v0 = q0[0]*yp[i0[0]] + q0[1]*yp[i0[1]] + q0[2]*yp[i0[2]] + q0[3]*yp[i0[3]];
            const int* i1 = i0 + 4; const float* q1 = q0 + 4;
            float v1 = q1[0]*yp[i1[0]] + q1[1]*yp[i1[1]] + q1[2]*yp[i1[2]] + q1[3]*yp[i1[3]];
            samp2[(t9*8 + c)*32 + (((P & 3) << 3) | (P >> 2))] = make_float2(v0, v1);
        }
        {
            float4* wdst = (float4*)wsh2;
            for (int e4 = tid; e4 < 3456; e4 += 256) {
                int t9 = e4 / 384; int off4 = e4 - t9*384;
                wdst[e4] = g_defw2[(size_t)(t9*96 + c0)*48 + off4];
            }
        }
        __syncthreads();
        #pragma unroll 3
        for (int t9 = 0; t9 < 9; t9++) {
            #pragma unroll
            for (int c = 0; c < 8; c++) {
                const float2* sp = &samp2[(t9*8 + c)*32];
                u64 s0 = *(const u64*)&sp[0*8 + pg];
                u64 s1 = *(const u64*)&sp[1*8 + pg];
                u64 s2 = *(const u64*)&sp[2*8 + pg];
                u64 s3 = *(const u64*)&sp[3*8 + pg];
                const float2* wb = &wsh2[(t9*8 + c)*96];
                #pragma unroll
                for (int k = 0; k < 3; k++) {
                    u64 wp2 = *(const u64*)&wb[og + 32*k];
                    pacc[k][0] = ffma2(wp2, s0, pacc[k][0]);
                    pacc[k][1] = ffma2(wp2, s1, pacc[k][1]);
                    pacc[k][2] = ffma2(wp2, s2, pacc[k][2]);
                    pacc[k][3] = ffma2(wp2, s3, pacc[k][3]);
                }
            }
        }
    }
    #pragma unroll
    for (int k = 0; k < 3; k++) {
        int o = og + 32*k;
        float bb = defb[o];
        size_t rowoff = (size_t)h*Wn + w0 + pg*8;
        float* zp = g_z + ((size_t)(b*Cn + o))*HWn + rowoff;
        const float* yb = g_ybase + ((size_t)(b*Cn + o))*HWn + rowoff;
        const float* gp = g_gate + (size_t)b*HWn + rowoff;
        #pragma unroll
        for (int q = 0; q < 4; q++) {
            float2 f = unpack2(pacc[k][q]);
            float g0 = gp[2*q], g1 = gp[2*q+1];
            zp[2*q]   = (1.f - g0)*yb[2*q]   + g0*(f.x + bb);
            zp[2*q+1] = (1.f - g1)*yb[2*q+1] + g1*(f.y + bb);
        }
    }
}

// ------------------------- batchnorm (float4) -------------------------------
__global__ void bn_stats_k() {
    __shared__ float ss[256], ss2[256];
    int c = blockIdx.x, tid = threadIdx.x;
    float s = 0.f, s2 = 0.f;
    for (int b = 0; b < Bn; b++) {
        const float4* zp = (const float4*)(g_z + ((size_t)(b*Cn + c))*HWn);
        for (int i = tid; i < HWn/4; i += 256) {
            float4 v = zp[i];
            s += v.x + v.y + v.z + v.w;
            s2 += v.x*v.x + v.y*v.y + v.z*v.z + v.w*v.w;
        }
    }
    ss[tid] = s; ss2[tid] = s2;
    __syncthreads();
    for (int st = 128; st > 0; st >>= 1) {
        if (tid < st) { ss[tid] += ss[tid+st]; ss2[tid] += ss2[tid+st]; }
        __syncthreads();
    }
    if (tid == 0) {
        float inv = 1.f/(float)(Bn*HWn);
        float mu = ss[0]*inv;
        float var = ss2[0]*inv - mu*mu;
        g_mu[c] = mu;
        g_istd[c] = rsqrtf(var + 1e-5f);
    }
}

__global__ void bn_apply_k(const float* __restrict__ x,
                           const float* __restrict__ gam, const float* __restrict__ bet,
                           float* __restrict__ out) {
    int e = blockIdx.x*256 + threadIdx.x;
    int c = blockIdx.y, b = blockIdx.z;
    size_t i4 = ((size_t)(b*Cn + c))*(HWn/4) + e;
    float sc2 = g_istd[c]*gam[c];
    float sh = bet[c] - g_mu[c]*sc2;
    float4 z = ((const float4*)g_z)[i4];
    float4 xv = ((const float4*)x)[i4];
    float4 o;
    o.x = fmaxf(z.x*sc2 + sh + xv.x, 0.f);
    o.y = fmaxf(z.y*sc2 + sh + xv.y, 0.f);
    o.z = fmaxf(z.z*sc2 + sh + xv.z, 0.f);
    o.w = fmaxf(z.w*sc2 + sh + xv.w, 0.f);
    ((float4*)out)[i4] = o;
}

// ------------------------- launch -------------------------------------------
extern "C" void kernel_launch(void* const* d_in, const int* in_sizes, int n_in,
                              void* d_out, int out_size) {
    const float* x     = (const float*)d_in[0];
    const float* fdh_w = (const float*)d_in[1];
    const float* fdh_b = (const float*)d_in[2];
    const float* fdw_w = (const float*)d_in[3];
    const float* fdw_b = (const float*)d_in[4];
    const float* cp1_w = (const float*)d_in[5];
    const float* cp1_b = (const float*)d_in[6];
    const float* cp2_w = (const float*)d_in[7];
    const float* cp2_b = (const float*)d_in[8];
    const float* sdh_w = (const float*)d_in[9];
    const float* sdh_b = (const float*)d_in[10];
    const float* sdw_w = (const float*)d_in[11];
    const float* sdw_b = (const float*)d_in[12];
    const float* sr1_w = (const float*)d_in[13];
    const float* sr1_b = (const float*)d_in[14];
    const float* sr2_w = (const float*)d_in[15];
    const float* sr2_b = (const float*)d_in[16];
    const float* off_w = (const float*)d_in[17];
    const float* off_b = (const float*)d_in[18];
    const float* dg1_w = (const float*)d_in[19];
    const float* dg1_b = (const float*)d_in[20];
    const float* dg2_w = (const float*)d_in[21];
    const float* dg2_b = (const float*)d_in[22];
    const float* base_w = (const float*)d_in[23];
    const float* base_b = (const float*)d_in[24];
    const float* def_w = (const float*)d_in[25];
    const float* def_b = (const float*)d_in[26];
    const float* bn_g  = (const float*)d_in[27];
    const float* bn_b  = (const float*)d_in[28];
    float* out = (float*)d_out;

    float *p_fe, *p_fem;
    cudaGetSymbolAddress((void**)&p_fe, g_fe);
    cudaGetSymbolAddress((void**)&p_fem, g_fem);

    const int FREQ_SMEM = 128*132*4;         // 67584 B
    const int DEF_SMEM  = 23040 * 4;         // 92160 B
    const int C96_SMEM  = 8*96*9*8;          // 55296 B
    const int C68_SMEM  = 8*68*9*8;          // 39168 B
    cudaFuncSetAttribute(freq_fused_k, cudaFuncAttributeMaxDynamicSharedMemorySize, FREQ_SMEM);
    cudaFuncSetAttribute(deform_combine_k, cudaFuncAttributeMaxDynamicSharedMemorySize, DEF_SMEM);
    cudaFuncSetAttribute(conv_base_k, cudaFuncAttributeMaxDynamicSharedMemorySize, C96_SMEM);
    cudaFuncSetAttribute(convoffdg_k, cudaFuncAttributeMaxDynamicSharedMemorySize, C68_SMEM);

    bool fork = g_sync.ok;
    cudaStream_t sB = fork ? g_sync.s1 : 0;

    // ---- prep (single kernel) ----
    prep_all_k<<<CDIV(96*96*9,256), 256>>>(off_w, dg1_w, base_w, def_w);
    // ---- FFT(x) -> mag ----
    fft_rows_k<<<dim3(Hn/2, Cn, Bn), 128>>>(x, Cn);
    fft_cols_k<<<dim3(9, Cn, Bn), 128>>>();
    // ---- fork: fe + spatial branch (sB) || freq branch (main) ----
    if (fork) {
        cudaEventRecord(g_sync.ev1, 0);
        cudaStreamWaitEvent(sB, g_sync.ev1, 0);
    }
    chan_mean_k<<<dim3(Hn, Bn), 512, 0, sB>>>(p_fe);
    spatial_in_k<<<dim3(Hn, Bn), 256, 0, sB>>>(x);
    sp_fused_k<<<dim3(Hn, Bn), 256, 0, sB>>>(sdh_w, sdh_b, sdw_w, sdw_b,
                                             sr1_w, sr1_b, sr2_w, sr2_b);
    freq_fused_k<<<dim3(Cn, Bn), 512, FREQ_SMEM>>>(fdh_w, fdh_b, fdw_w, fdw_b);
    ca_mlp_k<<<Bn, 96>>>(cp1_w, cp1_b, cp2_w, cp2_b);
    if (fork) {
        cudaEventRecord(g_sync.evA, sB);
        cudaStreamWaitEvent(0, g_sync.evA, 0);
    }
    // ---- y = x*ca*sa (into aux ch 0..95) + FFT(y) rows ----
    fft_rows_y_k<<<dim3(Hn/2, Cn, Bn), 128>>>(x);
    // ---- fork: conv_base starts NOW on sB (needs only aux ch 0..95) ----
    if (fork) {
        cudaEventRecord(g_sync.ev2, 0);
        cudaStreamWaitEvent(sB, g_sync.ev2, 0);
    }
    conv_base_k<<<1024, 256, C96_SMEM, sB>>>(base_b);
    // ---- main: fem chain + auxmisc + convoffdg ----
    fft_cols_k<<<dim3(9, Cn, Bn), 128>>>();
    chan_mean_k<<<dim3(Hn, Bn), 512>>>(p_fem);
    auxmisc_k<<<dim3(Hn, Bn), 256>>>();
    convoffdg_k<<<1024, 256, C68_SMEM>>>(off_b, dg1_b, dg2_w, dg2_b);
    if (fork) {
        cudaEventRecord(g_sync.evB, sB);
        cudaStreamWaitEvent(0, g_sync.evB, 0);
    }
    // ---- deformable ----
    deform_combine_k<<<1024, 256, DEF_SMEM>>>(def_b);
    // ---- BN + residual relu ----
    bn_stats_k<<<Cn, 256>>>();
    bn_apply_k<<<dim3(HWn/1024, Cn, Bn), 256>>>(x, bn_g, bn_b, out);
}

// round 15
// speedup vs baseline: 1.0511x; 1.0013x over previous
#include <cuda_runtime.h>
#include <math.h>

#define Bn 2
#define Cn 96
#define Hn 128
#define Wn 256
#define WFn 129
#define HWn (Hn*Wn)
#define AUXn 101
#define MIDn 24
#define DMIDn 50
#define NTOT (Bn*Cn*HWn)
#define NF (Bn*Cn*Hn*WFn)
#define CDIV(a,b) (((a)+(b)-1)/(b))
#define DEFBLK 1024

typedef unsigned long long u64;

__device__ __forceinline__ u64 ffma2(u64 a, u64 b, u64 c) {
    u64 d;
    asm("fma.rn.f32x2 %0, %1, %2, %3;" : "=l"(d) : "l"(a), "l"(b), "l"(c));
    return d;
}
__device__ __forceinline__ float2 unpack2(u64 v) {
    float2 d; asm("mov.b64 {%0, %1}, %2;" : "=f"(d.x), "=f"(d.y) : "l"(v)); return d;
}

// ------------------------- scratch (static device memory) -------------------
static __device__ float2 g_tw[128];
static __device__ float2 g_fft[(size_t)NF];
static __device__ float g_mag[NF];
static __device__ float g_fe[Bn*Hn*WFn];
static __device__ float g_fem[Bn*Hn*WFn];
static __device__ float g_gvec[Bn*3*Cn];
static __device__ float g_ca[Bn*Cn];
static __device__ float g_s0[Bn*3*HWn];
static __device__ float g_sa[Bn*HWn];
static __device__ float g_aux[(size_t)Bn*AUXn*HWn];
static __device__ float g_offb[Bn*18*HWn];
static __device__ float g_gate[Bn*HWn];
static __device__ float g_ybase[NTOT];
static __device__ float g_z[NTOT];
static __device__ float g_mu[Cn];
static __device__ float g_istd[Cn];
static __device__ float g_bsum[DEFBLK*96];
static __device__ float g_bsumsq[DEFBLK*96];
// pre-packed duplicated (w,w) weight tables (float4-aligned)
static __device__ float4 g_wpk68[31824];   // [104][68][9] float2
static __device__ float4 g_wpk96[41472];   // [96][96][9] float2
static __device__ float4 g_defw2[41472];   // [9][96][96] float2

// ------------------------- stream/event infra (static init) -----------------
struct SyncInfra {
    cudaStream_t s1;
    cudaEvent_t evF, ev1, evA, ev2, evB, evW;
    bool ok;
    SyncInfra() {
        ok = true;
        if (cudaStreamCreateWithFlags(&s1, cudaStreamNonBlocking) != cudaSuccess) { ok = false; s1 = 0; return; }
        if (cudaEventCreateWithFlags(&evF, cudaEventDisableTiming) != cudaSuccess) { ok = false; return; }
        if (cudaEventCreateWithFlags(&ev1, cudaEventDisableTiming) != cudaSuccess) { ok = false; return; }
        if (cudaEventCreateWithFlags(&evA, cudaEventDisableTiming) != cudaSuccess) { ok = false; return; }
        if (cudaEventCreateWithFlags(&ev2, cudaEventDisableTiming) != cudaSuccess) { ok = false; return; }
        if (cudaEventCreateWithFlags(&evB, cudaEventDisableTiming) != cudaSuccess) { ok = false; return; }
        if (cudaEventCreateWithFlags(&evW, cudaEventDisableTiming) != cudaSuccess) { ok = false; return; }
    }
};
static SyncInfra g_sync;

// ------------------------- prep kernels --------------------------------------
__global__ void prep_tw_k() {
    int j = threadIdx.x;           // 128
    float ang = -6.2831853071795864f * (float)j / 256.f;
    float s, c; sincosf(ang, &s, &c);
    g_tw[j] = make_float2(c, s);
}
__global__ void prep_wpack_k(const float* __restrict__ offw, const float* __restrict__ dg1w,
                             const float* __restrict__ basew, const float* __restrict__ defw) {
    int i = blockIdx.x*256 + threadIdx.x;
    if (i < 104*68*9) {
        int ci = i / 612; int rem = i - ci*612; int o = rem / 9; int j = rem - o*9;
        float v = 0.f;
        if (ci < AUXn) {
            if (o < 18) v = offw[((size_t)o*AUXn + ci)*9 + j];
            else        v = dg1w[((size_t)(o-18)*AUXn + ci)*9 + j];
        }
        ((float2*)g_wpk68)[i] = make_float2(v, v);
    }
    if (i < 96*96*9) {
        int ci = i / 864; int rem = i - ci*864; int o = rem / 9; int j = rem - o*9;
        float v = basew[((size_t)o*96 + ci)*9 + j];
        ((float2*)g_wpk96)[i] = make_float2(v, v);
        int o2 = i % 96; int c2 = (i / 96) % 96; int t2 = i / (96*96);
        float v2 = defw[((size_t)o2*96 + c2)*9 + t2];
        ((float2*)g_defw2)[i] = make_float2(v2, v2);
    }
}

// ------------------------- FFT kernels (split, high-parallel) ---------------
__global__ void fft_rows_k(const float* __restrict__ in, int cstride) {
    __shared__ float re[256], im[256];
    __shared__ float2 tws[128];
    int h0 = blockIdx.x * 2;
    int c = blockIdx.y, b = blockIdx.z;
    const float* r0 = in + ((size_t)(b*cstride + c)*Hn + h0)*Wn;
    const float* r1 = r0 + Wn;
    int tid = threadIdx.x;                // 128
    tws[tid] = g_tw[tid];
    for (int i = tid; i < 256; i += 128) {
        int j = __brev((unsigned)i) >> 24;
        re[j] = r0[i];
        im[j] = r1[i];
    }
    __syncthreads();
    #pragma unroll
    for (int s = 1; s <= 8; s++) {
        int half = 1 << (s - 1);
        int i = tid;
        int off = i & (half - 1);
        int a = ((i >> (s - 1)) << s) + off;
        int bb = a + half;
        float2 tw = tws[off << (8 - s)];
        float br = re[bb], bi = im[bb];
        float ar = re[a],  ai = im[a];
        float xr = br*tw.x - bi*tw.y;
        float xi = br*tw.y + bi*tw.x;
        re[a] = ar + xr; im[a] = ai + xi;
        re[bb] = ar - xr; im[bb] = ai - xi;
        __syncthreads();
    }
    float2* out0 = g_fft + ((size_t)(b*Cn + c)*Hn + h0)*WFn;
    float2* out1 = out0 + WFn;
    int k = tid;
    float zr = re[k], zi = im[k];
    int km = (256 - k) & 255;
    float wr = re[km], wi = im[km];
    out0[k] = make_float2(0.5f*(zr + wr), 0.5f*(zi - wi));
    out1[k] = make_float2(0.5f*(zi + wi), -0.5f*(zr - wr));
    if (tid == 0) {
        out0[128] = make_float2(re[128], 0.f);
        out1[128] = make_float2(im[128], 0.f);
    }
}

// fused: y = x*ca*sa (written to g_aux) + row FFT of y
__global__ void fft_rows_y_k(const float* __restrict__ x) {
    __shared__ float re[256], im[256];
    __shared__ float2 tws[128];
    int h0 = blockIdx.x * 2;
    int c = blockIdx.y, b = blockIdx.z;
    const float* r0 = x + ((size_t)(b*Cn + c)*Hn + h0)*Wn;
    const float* r1 = r0 + Wn;
    float* y0 = g_aux + ((size_t)(b*AUXn + c)*Hn + h0)*Wn;
    float* y1 = y0 + Wn;
    const float* sa0 = g_sa + (size_t)b*HWn + h0*Wn;
    const float* sa1 = sa0 + Wn;
    float cav = g_ca[b*Cn + c];
    int tid = threadIdx.x;                // 128
    tws[tid] = g_tw[tid];
    for (int i = tid; i < 256; i += 128) {
        int j = __brev((unsigned)i) >> 24;
        float v0 = r0[i]*cav*sa0[i];
        float v1 = r1[i]*cav*sa1[i];
        y0[i] = v0; y1[i] = v1;
        re[j] = v0;
        im[j] = v1;
    }
    __syncthreads();
    #pragma unroll
    for (int s = 1; s <= 8; s++) {
        int half = 1 << (s - 1);
        int i = tid;
        int off = i & (half - 1);
        int a = ((i >> (s - 1)) << s) + off;
        int bb = a + half;
        float2 tw = tws[off << (8 - s)];
        float br = re[bb], bi = im[bb];
        float ar = re[a],  ai = im[a];
        float xr = br*tw.x - bi*tw.y;
        float xi = br*tw.y + bi*tw.x;
        re[a] = ar + xr; im[a] = ai + xi;
        re[bb] = ar - xr; im[bb] = ai - xi;
        __syncthreads();
    }
    float2* out0 = g_fft + ((size_t)(b*Cn + c)*Hn + h0)*WFn;
    float2* out1 = out0 + WFn;
    int k = tid;
    float zr = re[k], zi = im[k];
    int km = (256 - k) & 255;
    float wr = re[km], wi = im[km];
    out0[k] = make_float2(0.5f*(zr + wr), 0.5f*(zi - wi));
    out1[k] = make_float2(0.5f*(zi + wi), -0.5f*(zr - wr));
    if (tid == 0) {
        out0[128] = make_float2(re[128], 0.f);
        out1[128] = make_float2(im[128], 0.f);
    }
}

// 128-pt FFT down columns, 16 columns per block (coalesced), |.| * 1/sqrt(HW)
__global__ void fft_cols_k() {
    __shared__ float cre[16][129];
    __shared__ float cim[16][129];
    __shared__ float2 tws[128];
    int kb = blockIdx.x;                  // 0..8
    int c = blockIdx.y, b = blockIdx.z;
    int bc = b*Cn + c;
    int k0 = kb * 16;
    int ncols = (kb < 8) ? 16 : 1;
    int lg = (kb < 8) ? 4 : 0;
    int tid = threadIdx.x;                // 128
    tws[tid] = g_tw[tid];
    int kk = tid & 15, ht = tid >> 4;
    const float2* src = g_fft + (size_t)bc*Hn*WFn;
    for (int hb = 0; hb < 16; hb++) {
        int h = hb*8 + ht;
        if (kk < ncols) {
            float2 v = src[(size_t)h*WFn + k0 + kk];
            int j = __brev((unsigned)h) >> 25;
            cre[kk][j] = v.x; cim[kk][j] = v.y;
        }
    }
    __syncthreads();
    #pragma unroll
    for (int s = 1; s <= 7; s++) {
        int half = 1 << (s - 1);
        int total = ncols << 6;
        for (int e = tid; e < total; e += 128) {
            int col = e & (ncols - 1);
            int i = e >> lg;
            int off = i & (half - 1);
            int a = ((i >> (s - 1)) << s) + off;
            int bb = a + half;
            float2 tw = tws[off << (8 - s)];
            float br = cre[col][bb], bi = cim[col][bb];
            float ar = cre[col][a],  ai = cim[col][a];
            float xr = br*tw.x - bi*tw.y;
            float xi = br*tw.y + bi*tw.x;
            cre[col][a] = ar + xr; cim[col][a] = ai + xi;
            cre[col][bb] = ar - xr; cim[col][bb] = ai - xi;
        }
        __syncthreads();
    }
    const float sc = 0.0055242717280199026f;  // 1/sqrt(128*256)
    float* dst = g_mag + (size_t)bc*Hn*WFn;
    int total = ncols << 7;
    for (int e = tid; e < total; e += 128) {
        int col = e & (ncols - 1);
        int h = e >> lg;
        float r = cre[col][h], m = cim[col][h];
        dst[(size_t)h*WFn + k0 + col] = sqrtf(r*r + m*m) * sc;
    }
}

// mean over channels of g_mag -> out[b][h][k] (4-way channel-parallel)
__global__ __launch_bounds__(512)
void chan_mean_k(float* __restrict__ out) {
    __shared__ float part[4][132];
    int h = blockIdx.x, b = blockIdx.y;
    int tid = threadIdx.x;                // 512
    int cg = tid >> 7, lk = tid & 127;
    const float* p0 = g_mag + ((size_t)(b*Cn + cg*24)*Hn + h)*WFn;
    for (int k = lk; k < WFn; k += 128) {
        float s = 0.f;
        #pragma unroll 6
        for (int c = 0; c < 24; c++) s += p0[(size_t)c*Hn*WFn + k];
        part[cg][k] = s;
    }
    __syncthreads();
    if (tid < WFn) {
        float s = part[0][tid] + part[1][tid] + part[2][tid] + part[3][tid];
        out[(size_t)(b*Hn + h)*WFn + tid] = s * (1.f/Cn);
    }
}

// --------- fused freq branch: direct 49-tap separable stencil + pools -------
__global__ __launch_bounds__(512)
void freq_fused_k(const float* __restrict__ w7h, const float* __restrict__ b7h,
                  const float* __restrict__ w7w, const float* __restrict__ b7w) {
    extern __shared__ float A[];          // [128][132]
    __shared__ float S[4][132];
    __shared__ float bins[21];
    int c = blockIdx.x, b = blockIdx.y;
    int tid = threadIdx.x;
    const float* mp = g_mag + (size_t)(b*Cn + c)*Hn*WFn;
    for (int e = tid; e < 128*129; e += 512) {
        int h = e / 129, k = e - h*129;
        A[h*132 + k] = mp[e];
    }
    float wh[7], ww[7];
    #pragma unroll
    for (int d = 0; d < 7; d++) { wh[d] = w7h[c*7+d]; ww[d] = w7w[c*7+d]; }
    float bh = b7h[c], bw = b7w[c];
    __syncthreads();
    for (int t = tid; t < 4*129; t += 512) {
        int band = t / 129, k = t - band*129;
        float acc = 0.f;
        for (int hh = 0; hh < 32; hh++) {
            int h = band*32 + hh;
            float t2 = bw;
            #pragma unroll
            for (int d = 0; d < 7; d++) {
                int kk = k + d - 3;
                if (kk >= 0 && kk < 129) {
                    float t1 = bh;
                    #pragma unroll
                    for (int e = 0; e < 7; e++) {
                        int h2 = h + e - 3;
                        if (h2 >= 0 && h2 < 128) t1 += wh[e]*A[h2*132 + kk];
                    }
                    t2 += ww[d]*t1;
                }
            }
            acc += t2;
        }
        S[band][k] = acc;
    }
    __syncthreads();
    if (tid < 16) {
        int i = tid >> 2, j = tid & 3;
        int ws = (j*WFn)/4, we = ((j+1)*WFn + 3)/4;
        float s = 0;
        for (int k = ws; k < we; k++) s += S[i][k];
        bins[tid] = s / (32.f * (float)(we - ws));
    } else if (tid < 20) {
        int t2 = tid - 16; int i = t2 >> 1, j = t2 & 1;
        int ws = (j*WFn)/2, we = ((j+1)*WFn + 1)/2;
        float s = 0;
        for (int k = ws; k < we; k++) s += S[2*i][k] + S[2*i+1][k];
        bins[tid] = s / (64.f * (float)(we - ws));
    } else if (tid == 20) {
        float s = 0;
        for (int k = 0; k < WFn; k++) s += S[0][k]+S[1][k]+S[2][k]+S[3][k];
        bins[20] = s / (128.f*129.f);
    }
    __syncthreads();
    if (tid == 0) {
        float g2 = bins[16]+bins[17]+bins[18]+bins[19];
        float g3 = 0;
        for (int m = 0; m < 16; m++) g3 += bins[m];
        g_gvec[b*288 + c]        = bins[20];
        g_gvec[b*288 + Cn + c]   = g2 * 0.25f;
        g_gvec[b*288 + 2*Cn + c] = g3 * 0.0625f;
    }
}

// ------------------------- channel-attention MLP ----------------------------
__global__ void ca_mlp_k(const float* __restrict__ w1, const float* __restrict__ b1,
                         const float* __restrict__ w2, const float* __restrict__ b2) {
    __shared__ float gs[288], hs[MIDn];
    int b = blockIdx.x, tid = threadIdx.x;   // 96 threads
    for (int i = tid; i < 288; i += 96) gs[i] = g_gvec[b*288 + i];
    __syncthreads();
    if (tid < MIDn) {
        float a = b1[tid];
        for (int k = 0; k < 288; k++) a += w1[tid*288 + k]*gs[k];
        hs[tid] = fmaxf(a, 0.f);
    }
    __syncthreads();
    float a = b2[tid];
    #pragma unroll
    for (int m = 0; m < MIDn; m++) a += w2[tid*MIDn + m]*hs[m];
    g_ca[b*Cn + tid] = 1.f/(1.f + expf(-a));
}

// ------------------------- spatial branch -----------------------------------
__global__ void spatial_in_k(const float* __restrict__ x) {
    int h = blockIdx.x, b = blockIdx.y;
    int w = threadIdx.x;                  // 256
    int hw = h*Wn + w;
    const float* xp = x + (size_t)b*Cn*HWn + hw;
    float s = 0.f, s2 = 0.f;
    #pragma unroll 4
    for (int c = 0; c < Cn; c++) { float v = xp[(size_t)c*HWn]; s += v; s2 += v*v; }
    float mean = s * (1.f/Cn);
    float l2 = sqrtf(s2 * (1.f/Cn) + 1e-6f);
    float src = ((float)w + 0.5f)*(129.f/256.f) - 0.5f;
    float f0 = floorf(src); int i0 = (int)f0; float fr = src - f0;
    int ia = min(max(i0, 0), WFn-1), ib = min(max(i0+1, 0), WFn-1);
    const float* fp = g_fe + (size_t)(b*Hn + h)*WFn;
    float fv = fp[ia]*(1.f - fr) + fp[ib]*fr;
    g_s0[((size_t)(b*3+0))*HWn + hw] = mean;
    g_s0[((size_t)(b*3+1))*HWn + hw] = l2;
    g_s0[((size_t)(b*3+2))*HWn + hw] = fv;
}

// fused dwsp_h + dwsp_w + sr: one block per (h, b); 256 threads (w)
__global__ __launch_bounds__(256)
void sp_fused_k(const float* __restrict__ w15h, const float* __restrict__ b15h,
                const float* __restrict__ w15w, const float* __restrict__ b15w,
                const float* __restrict__ sr1w, const float* __restrict__ sr1b,
                const float* __restrict__ sr2w, const float* __restrict__ sr2b) {
    __shared__ float s1buf[3][3][272];
    __shared__ float sbuf[3][3][258];
    __shared__ float wsm[3][15], wsw[3][15];
    int h = blockIdx.x, b = blockIdx.y;
    int w = threadIdx.x;                 // 256
    if (w < 45) { wsm[w/15][w%15] = w15h[w]; wsw[w/15][w%15] = w15w[w]; }
    if (w < 7) {
        #pragma unroll
        for (int ch = 0; ch < 3; ch++)
            #pragma unroll
            for (int j = 0; j < 3; j++) { s1buf[ch][j][w] = 0.f; s1buf[ch][j][263+w] = 0.f; }
    }
    if (w < 9) {
        #pragma unroll
        for (int ch = 0; ch < 3; ch++)
            #pragma unroll
            for (int j = 0; j < 3; j++) s1buf[ch][j][263+w] = 0.f;
    }
    if (w < 3) {
        #pragma unroll
        for (int ch = 0; ch < 3; ch++) { sbuf[ch][w][0] = 0.f; sbuf[ch][w][257] = 0.f; }
    }
    __syncthreads();
    #pragma unroll
    for (int ch = 0; ch < 3; ch++) {
        const float* s0p = g_s0 + ((size_t)(b*3 + ch))*HWn + w;
        #pragma unroll
        for (int j = 0; j < 3; j++) {
            int hr = h + j - 1;
            float a = b15h[ch];
            #pragma unroll
            for (int d = 0; d < 15; d++) {
                int hh = hr + d - 7;
                if (hh >= 0 && hh < Hn) a += wsm[ch][d]*s0p[hh*Wn];
            }
            s1buf[ch][j][7 + w] = a;
        }
    }
    __syncthreads();
    #pragma unroll
    for (int ch = 0; ch < 3; ch++) {
        #pragma unroll
        for (int j = 0; j < 3; j++) {
            float a = b15w[ch];
            #pragma unroll
            for (int d = 0; d < 15; d++) a += wsw[ch][d]*s1buf[ch][j][w + d];
            sbuf[ch][j][1 + w] = a;
        }
    }
    __syncthreads();
    float acc = sr2b[0];
    #pragma unroll
    for (int ch = 0; ch < 3; ch++) {
        float v = sr1b[ch];
        #pragma unroll
        for (int ky = 0; ky < 3; ky++) {
            int hh = h + ky - 1; if (hh < 0 || hh >= Hn) continue;
            #pragma unroll
            for (int kx = 0; kx < 3; kx++) {
                v += sr1w[ch*9 + ky*3 + kx]*sbuf[ch][ky][w + kx];
            }
        }
        acc += sr2w[ch]*fmaxf(v, 0.f);
    }
    g_sa[(size_t)b*HWn + h*Wn + w] = 1.f/(1.f + expf(-acc));
}

__global__ void auxmisc_k() {
    int h = blockIdx.x, b = blockIdx.y;
    int w = threadIdx.x;                 // 256
    int hw = h*Wn + w;
    float theta = -3.14159265358979324f + (float)w * (6.2831853071795864f/255.f);
    float phi   = -1.57079632679489662f + (float)h * (3.14159265358979324f/127.f);
    size_t base = (size_t)b*AUXn*HWn + hw;
    g_aux[base + (size_t)96*HWn] = sinf(theta);
    g_aux[base + (size_t)97*HWn] = cosf(theta);
    g_aux[base + (size_t)98*HWn] = sinf(phi);
    g_aux[base + (size_t)99*HWn] = cosf(phi);
    float src = ((float)w + 0.5f)*(129.f/256.f) - 0.5f;
    float f0 = floorf(src); int i0 = (int)f0; float fr = src - f0;
    int ia = min(max(i0, 0), WFn-1), ib = min(max(i0+1, 0), WFn-1);
    const float* fp = g_fem + (size_t)(b*Hn + h)*WFn;
    g_aux[base + (size_t)100*HWn] = fp[ia]*(1.f - fr) + fp[ib]*fr;
}

// ------------- merged offset(18)+dg1(50) conv, pre-packed weights -----------
__global__ __launch_bounds__(256)
void convoffdg_k(const float* __restrict__ offbias,
                 const float* __restrict__ dg1b,
                 const float* __restrict__ dg2w, const float* __restrict__ dg2b) {
    constexpr int COUT = 68;
    constexpr int NO = 3;
    constexpr int CB = 8;
    __shared__ float2 tile2[CB][3][66];
    __shared__ float sgate[32][64];
    extern __shared__ float2 wdyn[];          // [CB][COUT*9]
    int bx = blockIdx.x;
    int seg = bx & 3; int h = (bx >> 2) & (Hn - 1); int b = bx >> 9;
    int w0 = seg * 64;
    int tid = threadIdx.x;
    int pg = tid & 7, og = tid >> 3;
    u64 pacc[NO][4];
    #pragma unroll
    for (int k = 0; k < NO; k++)
        #pragma unroll
        for (int q = 0; q < 4; q++) pacc[k][q] = 0ull;
    const float* inb = g_aux + (size_t)b*AUXn*HWn;
    int pv8idx = (pg == 7) ? 64 : (pg + 1);
    for (int c0 = 0; c0 < AUXn; c0 += CB) {
        for (int m = tid; m < CB*3*65; m += 256) {
            int ci = m / 195; int rem = m - ci*195; int r = rem / 65; int p = rem - r*65;
            int l = (p < 64) ? (((p & 7) << 3) | (p >> 3)) : 64;
            int hh = h + r - 1, ww = w0 + l - 1;
            float v0 = 0.f, v1 = 0.f;
            if (c0 + ci < AUXn && hh >= 0 && hh < Hn) {
                const float* rowp = inb + (size_t)(c0 + ci)*HWn + (size_t)hh*Wn;
                if (ww >= 0 && ww < Wn) v0 = rowp[ww];
                if (ww + 1 >= 0 && ww + 1 < Wn) v1 = rowp[ww + 1];
            }
            tile2[ci][r][p] = make_float2(v0, v1);
        }
        {
            const float4* wsrc = g_wpk68 + (size_t)c0*306;
            float4* wdst = (float4*)wdyn;
            for (int m = tid; m < CB*306; m += 256) wdst[m] = wsrc[m];
        }
        __syncthreads();
        #pragma unroll 2
        for (int ci = 0; ci < CB; ci++) {
            #pragma unroll
            for (int r = 0; r < 3; r++) {
                const float2* trow = tile2[ci][r];
                u64 pv[9];
                #pragma unroll
                for (int j = 0; j < 8; j++) pv[j] = *(const u64*)&trow[j*8 + pg];
                pv[8] = *(const u64*)&trow[pv8idx];
                #pragma unroll
                for (int k = 0; k < NO; k++) {
                    int o = og + 32*k;
                    if (o >= COUT) break;
                    const u64* wp = (const u64*)&wdyn[ci*(COUT*9) + o*9 + r*3];
                    u64 wb0 = wp[0], wb1 = wp[1], wb2 = wp[2];
                    #pragma unroll
                    for (int q = 0; q < 4; q++) {
                        pacc[k][q] = ffma2(wb0, pv[2*q],   pacc[k][q]);
                        pacc[k][q] = ffma2(wb1, pv[2*q+1], pacc[k][q]);
                        pacc[k][q] = ffma2(wb2, pv[2*q+2], pacc[k][q]);
                    }
                }
            }
        }
        __syncthreads();
    }
    float part[8];
    #pragma unroll
    for (int p = 0; p < 8; p++) part[p] = 0.f;
    #pragma unroll
    for (int k = 0; k < NO; k++) {
        int o = og + 32*k;
        if (o >= COUT) break;
        if (o < 18) {
            float bb = offbias[o];
            float* op = g_offb + ((size_t)(b*18 + o))*HWn + h*Wn + w0 + pg*8;
            #pragma unroll
            for (int q = 0; q < 4; q++) {
                float2 f = unpack2(pacc[k][q]);
                op[2*q] = f.x + bb; op[2*q+1] = f.y + bb;
            }
        } else {
            float bb = dg1b[o-18];
            float wv = dg2w[o-18];
            #pragma unroll
            for (int q = 0; q < 4; q++) {
                float2 f = unpack2(pacc[k][q]);
                part[2*q]   += wv * fmaxf(f.x + bb, 0.f);
                part[2*q+1] += wv * fmaxf(f.y + bb, 0.f);
            }
        }
    }
    #pragma unroll
    for (int p = 0; p < 8; p++) sgate[og][pg*8 + p] = part[p];
    __syncthreads();
    if (tid < 64) {
        float s = dg2b[0];
        #pragma unroll 8
        for (int o2 = 0; o2 < 32; o2++) s += sgate[o2][tid];
        g_gate[(size_t)b*HWn + h*Wn + w0 + tid] = 1.f/(1.f + expf(-s));
    }
}

// ------------- base 3x3 conv (96->96), pre-packed weights -------------------
__global__ __launch_bounds__(256)
void conv_base_k(const float* __restrict__ baseb) {
    constexpr int COUT = 96;
    constexpr int NO = 3;
    constexpr int CB = 8;
    __shared__ float2 tile2[CB][3][66];
    extern __shared__ float2 wdyn[];          // [CB][COUT*9]
    int bx = blockIdx.x;
    int seg = bx & 3; int h = (bx >> 2) & (Hn - 1); int b = bx >> 9;
    int w0 = seg * 64;
    int tid = threadIdx.x;
    int pg = tid & 7, og = tid >> 3;
    u64 pacc[NO][4];
    #pragma unroll
    for (int k = 0; k < NO; k++)
        #pragma unroll
        for (int q = 0; q < 4; q++) pacc[k][q] = 0ull;
    const float* inb = g_aux + (size_t)b*AUXn*HWn;
    int pv8idx = (pg == 7) ? 64 : (pg + 1);
    for (int c0 = 0; c0 < 96; c0 += CB) {
        for (int m = tid; m < CB*3*65; m += 256) {
            int ci = m / 195; int rem = m - ci*195; int r = rem / 65; int p = rem - r*65;
            int l = (p < 64) ? (((p & 7) << 3) | (p >> 3)) : 64;
            int hh = h + r - 1, ww = w0 + l - 1;
            float v0 = 0.f, v1 = 0.f;
            if (hh >= 0 && hh < Hn) {
                const float* rowp = inb + (size_t)(c0 + ci)*HWn + (size_t)hh*Wn;
                if (ww >= 0 && ww < Wn) v0 = rowp[ww];
                if (ww + 1 >= 0 && ww + 1 < Wn) v1 = rowp[ww + 1];
            }
            tile2[ci][r][p] = make_float2(v0, v1);
        }
        {
            const float4* wsrc = g_wpk96 + (size_t)c0*432;
            float4* wdst = (float4*)wdyn;
            for (int m = tid; m < CB*432; m += 256) wdst[m] = wsrc[m];
        }
        __syncthreads();
        #pragma unroll 2
        for (int ci = 0; ci < CB; ci++) {
            #pragma unroll
            for (int r = 0; r < 3; r++) {
                const float2* trow = tile2[ci][r];
                u64 pv[9];
                #pragma unroll
                for (int j = 0; j < 8; j++) pv[j] = *(const u64*)&trow[j*8 + pg];
                pv[8] = *(const u64*)&trow[pv8idx];
                #pragma unroll
                for (int k = 0; k < NO; k++) {
                    int o = og + 32*k;
                    const u64* wp = (const u64*)&wdyn[ci*(COUT*9) + o*9 + r*3];
                    u64 wb0 = wp[0], wb1 = wp[1], wb2 = wp[2];
                    #pragma unroll
                    for (int q = 0; q < 4; q++) {
                        pacc[k][q] = ffma2(wb0, pv[2*q],   pacc[k][q]);
                        pacc[k][q] = ffma2(wb1, pv[2*q+1], pacc[k][q]);
                        pacc[k][q] = ffma2(wb2, pv[2*q+2], pacc[k][q]);
                    }
                }
            }
        }
        __syncthreads();
    }
    #pragma unroll
    for (int k = 0; k < NO; k++) {
        int o = og + 32*k;
        float bb = baseb[o];
        float* op = g_ybase + ((size_t)(b*COUT + o))*HWn + h*Wn + w0 + pg*8;
        #pragma unroll
        for (int q = 0; q < 4; q++) {
            float2 f = unpack2(pacc[k][q]);
            op[2*q] = f.x + bb; op[2*q+1] = f.y + bb;
        }
    }
}

// -------- deformable sampling + GEMM + combine + BN partial sums ------------
__global__ __launch_bounds__(256)
void deform_combine_k(const float* __restrict__ defb) {
    extern __shared__ float dsm[];
    float2* samp2 = (float2*)dsm;                    // 2304 float2
    float2* wsh2  = (float2*)(dsm + 4608);           // 6912 float2
    float*  s_w   = dsm + 18432;                     // 2304
    int*    s_idx = (int*)(dsm + 20736);             // 2304
    int bx = blockIdx.x;
    int seg = bx & 3; int h = (bx >> 2) & (Hn - 1); int b = bx >> 9;
    int w0 = seg * 64;
    int tid = threadIdx.x;
    int pg = tid & 7, og = tid >> 3;

    for (int e = tid; e < 576; e += 256) {
        int t9 = e >> 6, p = e & 63;
        int wpx = w0 + p;
        size_t obase = ((size_t)b*18)*HWn + (size_t)h*Wn + wpx;
        float ox = g_offb[obase + (size_t)(2*t9)*HWn];
        float oy = g_offb[obase + (size_t)(2*t9+1)*HWn];
        float px = (float)wpx + ox;
        float py = (float)h + oy;
        float x0 = floorf(px), y0 = floorf(py);
        float fx = px - x0, fy = py - y0;
        #pragma unroll
        for (int j = 0; j < 4; j++) {
            float xj = x0 + (float)(j & 1);
            float yj = y0 + (float)(j >> 1);
            float valid = (xj >= 0.f && xj <= 255.f && yj >= 0.f && yj <= 127.f) ? 1.f : 0.f;
            float xc = fminf(fmaxf(xj, 0.f), 255.f);
            float yc = fminf(fmaxf(yj, 0.f), 127.f);
            s_idx[(t9*64 + p)*4 + j] = (int)yc * Wn + (int)xc;
            float wx = (j & 1) ? fx : (1.f - fx);
            float wy = (j >> 1) ? fy : (1.f - fy);
            s_w[(t9*64 + p)*4 + j] = wx * wy * valid;
        }
    }

    u64 pacc[3][4];
    #pragma unroll
    for (int k = 0; k < 3; k++)
        #pragma unroll
        for (int q = 0; q < 4; q++) pacc[k][q] = 0ull;

    for (int c0 = 0; c0 < 96; c0 += 8) {
        __syncthreads();
        for (int e = tid; e < 2304; e += 256) {
            int t9 = e >> 8; int rem = e & 255; int c = rem >> 5; int P = rem & 31;
            int p0 = 2*P;
            const float* yp = g_aux + ((size_t)(b*AUXn + c0 + c))*HWn;
            const int* i0 = &s_idx[(t9*64 + p0)*4];
            const float* q0 = &s_w[(t9*64 + p0)*4];
            float v0 = q0[0]*yp[i0[0]] + q0[1]*yp[i0[1]] + q0[2]*yp[i0[2]] + q0[3]*yp[i0[3]];
            const int* i1 = i0 + 4; const float* q1 = q0 + 4;
            float v1 = q1[0]*yp[i1[0]] + q1[1]*yp[i1[1]] + q1[2]*yp[i1[2]] + q1[3]*yp[i1[3]];
            samp2[(t9*8 + c)*32 + (((P & 3) << 3) | (P >> 2))] = make_float2(v0, v1);
        }
        {
            float4* wdst = (float4*)wsh2;
            for (int e4 = tid; e4 < 3456; e4 += 256) {
                int t9 = e4 / 384; int off4 = e4 - t9*384;
                wdst[e4] = g_defw2[(size_t)(t9*96 + c0)*48 + off4];
            }
        }
        __syncthreads();
        #pragma unroll 3
        for (int t9 = 0; t9 < 9; t9++) {
            #pragma unroll
            for (int c = 0; c < 8; c++) {
                const float2* sp = &samp2[(t9*8 + c)*32];
                u64 s0 = *(const u64*)&sp[0*8 + pg];
                u64 s1 = *(const u64*)&sp[1*8 + pg];
                u64 s2 = *(const u64*)&sp[2*8 + pg];
                u64 s3 = *(const u64*)&sp[3*8 + pg];
                const float2* wb = &wsh2[(t9*8 + c)*96];
                #pragma unroll
                for (int k = 0; k < 3; k++) {
                    u64 wp2 = *(const u64*)&wb[og + 32*k];
                    pacc[k][0] = ffma2(wp2, s0, pacc[k][0]);
                    pacc[k][1] = ffma2(wp2, s1, pacc[k][1]);
                    pacc[k][2] = ffma2(wp2, s2, pacc[k][2]);
                    pacc[k][3] = ffma2(wp2, s3, pacc[k][3]);
                }
            }
        }
    }
    // epilogue: z = (1-gate)*y_base + gate*(acc + def_b); + BN partial sums
    #pragma unroll
    for (int k = 0; k < 3; k++) {
        int o = og + 32*k;
        float bb = defb[o];
        size_t rowoff = (size_t)h*Wn + w0 + pg*8;
        float* zp = g_z + ((size_t)(b*Cn + o))*HWn + rowoff;
        const float* yb = g_ybase + ((size_t)(b*Cn + o))*HWn + rowoff;
        const float* gp = g_gate + (size_t)b*HWn + rowoff;
        float zs = 0.f, zq = 0.f;
        #pragma unroll
        for (int q = 0; q < 4; q++) {
            float2 f = unpack2(pacc[k][q]);
            float g0 = gp[2*q], g1 = gp[2*q+1];
            float z0 = (1.f - g0)*yb[2*q]   + g0*(f.x + bb);
            float z1 = (1.f - g1)*yb[2*q+1] + g1*(f.y + bb);
            zp[2*q] = z0; zp[2*q+1] = z1;
            zs += z0 + z1;
            zq += z0*z0 + z1*z1;
        }
        #pragma unroll
        for (int off = 4; off > 0; off >>= 1) {
            zs += __shfl_down_sync(0xffffffffu, zs, off, 8);
            zq += __shfl_down_sync(0xffffffffu, zq, off, 8);
        }
        if (pg == 0) {
            g_bsum[(size_t)bx*96 + o] = zs;
            g_bsumsq[(size_t)bx*96 + o] = zq;
        }
    }
}

// ------------------------- batchnorm finalize + apply -----------------------
__global__ void bn_stats_k() {
    __shared__ float ss[256], ss2[256];
    int c = blockIdx.x, tid = threadIdx.x;
    float s = 0.f, s2 = 0.f;
    for (int i = tid; i < DEFBLK; i += 256) {
        s += g_bsum[(size_t)i*96 + c];
        s2 += g_bsumsq[(size_t)i*96 + c];
    }
    ss[tid] = s; ss2[tid] = s2;
    __syncthreads();
    for (int st = 128; st > 0; st >>= 1) {
        if (tid < st) { ss[tid] += ss[tid+st]; ss2[tid] += ss2[tid+st]; }
        __syncthreads();
    }
    if (tid == 0) {
        float inv = 1.f/(float)(Bn*HWn);
        float mu = ss[0]*inv;
        float var = ss2[0]*inv - mu*mu;
        g_mu[c] = mu;
        g_istd[c] = rsqrtf(var + 1e-5f);
    }
}

__global__ void bn_apply_k(const float* __restrict__ x,
                           const float* __restrict__ gam, const float* __restrict__ bet,
                           float* __restrict__ out) {
    int e = blockIdx.x*256 + threadIdx.x;
    int c = blockIdx.y, b = blockIdx.z;
    size_t i4 = ((size_t)(b*Cn + c))*(HWn/4) + e;
    float sc2 = g_istd[c]*gam[c];
    float sh = bet[c] - g_mu[c]*sc2;
    float4 z = ((const float4*)g_z)[i4];
    float4 xv = ((const float4*)x)[i4];
    float4 o;
    o.x = fmaxf(z.x*sc2 + sh + xv.x, 0.f);
    o.y = fmaxf(z.y*sc2 + sh + xv.y, 0.f);
    o.z = fmaxf(z.z*sc2 + sh + xv.z, 0.f);
    o.w = fmaxf(z.w*sc2 + sh + xv.w, 0.f);
    ((float4*)out)[i4] = o;
}

// ------------------------- launch -------------------------------------------
extern "C" void kernel_launch(void* const* d_in, const int* in_sizes, int n_in,
                              void* d_out, int out_size) {
    const float* x     = (const float*)d_in[0];
    const float* fdh_w = (const float*)d_in[1];
    const float* fdh_b = (const float*)d_in[2];
    const float* fdw_w = (const float*)d_in[3];
    const float* fdw_b = (const float*)d_in[4];
    const float* cp1_w = (const float*)d_in[5];
    const float* cp1_b = (const float*)d_in[6];
    const float* cp2_w = (const float*)d_in[7];
    const float* cp2_b = (const float*)d_in[8];
    const float* sdh_w = (const float*)d_in[9];
    const float* sdh_b = (const float*)d_in[10];
    const float* sdw_w = (const float*)d_in[11];
    const float* sdw_b = (const float*)d_in[12];
    const float* sr1_w = (const float*)d_in[13];
    const float* sr1_b = (const float*)d_in[14];
    const float* sr2_w = (const float*)d_in[15];
    const float* sr2_b = (const float*)d_in[16];
    const float* off_w = (const float*)d_in[17];
    const float* off_b = (const float*)d_in[18];
    const float* dg1_w = (const float*)d_in[19];
    const float* dg1_b = (const float*)d_in[20];
    const float* dg2_w = (const float*)d_in[21];
    const float* dg2_b = (const float*)d_in[22];
    const float* base_w = (const float*)d_in[23];
    const float* base_b = (const float*)d_in[24];
    const float* def_w = (const float*)d_in[25];
    const float* def_b = (const float*)d_in[26];
    const float* bn_g  = (const float*)d_in[27];
    const float* bn_b  = (const float*)d_in[28];
    float* out = (float*)d_out;

    float *p_fe, *p_fem;
    cudaGetSymbolAddress((void**)&p_fe, g_fe);
    cudaGetSymbolAddress((void**)&p_fem, g_fem);

    const int FREQ_SMEM = 128*132*4;         // 67584 B
    const int DEF_SMEM  = 23040 * 4;         // 92160 B
    const int C96_SMEM  = 8*96*9*8;          // 55296 B
    const int C68_SMEM  = 8*68*9*8;          // 39168 B
    cudaFuncSetAttribute(freq_fused_k, cudaFuncAttributeMaxDynamicSharedMemorySize, FREQ_SMEM);
    cudaFuncSetAttribute(deform_combine_k, cudaFuncAttributeMaxDynamicSharedMemorySize, DEF_SMEM);
    cudaFuncSetAttribute(conv_base_k, cudaFuncAttributeMaxDynamicSharedMemorySize, C96_SMEM);
    cudaFuncSetAttribute(convoffdg_k, cudaFuncAttributeMaxDynamicSharedMemorySize, C68_SMEM);

    bool fork = g_sync.ok;
    cudaStream_t sB = fork ? g_sync.s1 : 0;

    // ---- prep: twiddles on main; weight packing on sB AFTER a proper fork ----
    prep_tw_k<<<1, 128>>>();
    if (fork) {
        cudaEventRecord(g_sync.evF, 0);          // fork sB from the capture stream
        cudaStreamWaitEvent(sB, g_sync.evF, 0);
    }
    prep_wpack_k<<<CDIV(96*96*9,256), 256, 0, sB>>>(off_w, dg1_w, base_w, def_w);
    if (fork) cudaEventRecord(g_sync.evW, sB);
    // ---- FFT(x) -> mag ----
    fft_rows_k<<<dim3(Hn/2, Cn, Bn), 128>>>(x, Cn);
    fft_cols_k<<<dim3(9, Cn, Bn), 128>>>();
    // ---- fork: fe + spatial branch (sB) || freq branch (main) ----
    if (fork) {
        cudaEventRecord(g_sync.ev1, 0);
        cudaStreamWaitEvent(sB, g_sync.ev1, 0);
    }
    chan_mean_k<<<dim3(Hn, Bn), 512, 0, sB>>>(p_fe);
    spatial_in_k<<<dim3(Hn, Bn), 256, 0, sB>>>(x);
    sp_fused_k<<<dim3(Hn, Bn), 256, 0, sB>>>(sdh_w, sdh_b, sdw_w, sdw_b,
                                             sr1_w, sr1_b, sr2_w, sr2_b);
    freq_fused_k<<<dim3(Cn, Bn), 512, FREQ_SMEM>>>(fdh_w, fdh_b, fdw_w, fdw_b);
    ca_mlp_k<<<Bn, 96>>>(cp1_w, cp1_b, cp2_w, cp2_b);
    if (fork) {
        cudaEventRecord(g_sync.evA, sB);
        cudaStreamWaitEvent(0, g_sync.evA, 0);
    }
    // ---- y = x*ca*sa (into aux ch 0..95) + FFT(y) rows ----
    fft_rows_y_k<<<dim3(Hn/2, Cn, Bn), 128>>>(x);
    // ---- fork: conv_base starts NOW on sB (needs only aux ch 0..95 + weights) ----
    if (fork) {
        cudaEventRecord(g_sync.ev2, 0);
        cudaStreamWaitEvent(sB, g_sync.ev2, 0);
    }
    conv_base_k<<<1024, 256, C96_SMEM, sB>>>(base_b);
    // ---- main: fem chain + auxmisc + convoffdg ----
    fft_cols_k<<<dim3(9, Cn, Bn), 128>>>();
    chan_mean_k<<<dim3(Hn, Bn), 512>>>(p_fem);
    auxmisc_k<<<dim3(Hn, Bn), 256>>>();
    if (fork) cudaStreamWaitEvent(0, g_sync.evW, 0);   // packed weights ready
    convoffdg_k<<<1024, 256, C68_SMEM>>>(off_b, dg1_b, dg2_w, dg2_b);
    if (fork) {
        cudaEventRecord(g_sync.evB, sB);
        cudaStreamWaitEvent(0, g_sync.evB, 0);
    }
    // ---- deformable (+BN partial sums) ----
    deform_combine_k<<<DEFBLK, 256, DEF_SMEM>>>(def_b);
    // ---- BN finalize + apply ----
    bn_stats_k<<<Cn, 256>>>();
    bn_apply_k<<<dim3(HWn/1024, Cn, Bn), 256>>>(x, bn_g, bn_b, out);
}